// round 1
// baseline (speedup 1.0000x reference)
#include <cuda_runtime.h>
#include <math.h>

// Problem constants: B=4, L=1024, D=256, N_PER=48, N_HYP=16, K=64, feat 2K=128
#define M_ROWS 4096
#define DD 256
#define PI_F 3.14159265358979323846f

// scratch (static device globals; no allocation allowed)
__device__ float g_hidden[M_ROWS * DD];
__device__ float g_kp[M_ROWS * 48];
__device__ float g_qp[M_ROWS * 48];
__device__ float g_kh[M_ROWS * 32];
__device__ float g_qh[M_ROWS * 32];
__device__ float g_k2[M_ROWS * 128];
__device__ float g_q2[M_ROWS * 128];
__device__ float g_V[M_ROWS * DD];
__device__ float g_ret[M_ROWS * DD];
__device__ float g_rln[M_ROWS * DD];

__device__ __forceinline__ float gelu_exact(float v) {
    return 0.5f * v * (1.0f + erff(v * 0.7071067811865475f));
}

// ---------------------------------------------------------------------------
// Generic tiled GEMM: C[M,N] = act(A[M,256] @ W[N,256]^T + bias) (+ residual)
// ACT: 0 = bias only, 1 = bias + exact GELU, 2 = bias + residual add
// BM=BN=64, BK=32, 256 threads, 4x4 per-thread microtile.
// ---------------------------------------------------------------------------
template <int ACT>
__global__ void __launch_bounds__(256) gemm64(
    const float* __restrict__ A, const float* __restrict__ W,
    const float* __restrict__ bias, const float* __restrict__ R,
    float* __restrict__ C, int N)
{
    __shared__ float sA[32][65];  // [k][m], pad 65 -> conflict-free transposed stores
    __shared__ float sB[32][65];  // [k][n]
    const int tid = threadIdx.x;
    const int tx = tid & 15, ty = tid >> 4;
    const int m0 = blockIdx.x * 64, n0 = blockIdx.y * 64;

    float acc[4][4] = {};

    for (int k0 = 0; k0 < DD; k0 += 32) {
        #pragma unroll
        for (int s = 0; s < 2; s++) {
            int slot = tid + s * 256;       // 0..511
            int r = slot >> 3;              // 0..63
            int kk = (slot & 7) << 2;       // 0,4,...,28
            float4 va = *(const float4*)&A[(size_t)(m0 + r) * DD + k0 + kk];
            sA[kk + 0][r] = va.x; sA[kk + 1][r] = va.y;
            sA[kk + 2][r] = va.z; sA[kk + 3][r] = va.w;
            float4 vw = make_float4(0.f, 0.f, 0.f, 0.f);
            if (n0 + r < N)
                vw = *(const float4*)&W[(size_t)(n0 + r) * DD + k0 + kk];
            sB[kk + 0][r] = vw.x; sB[kk + 1][r] = vw.y;
            sB[kk + 2][r] = vw.z; sB[kk + 3][r] = vw.w;
        }
        __syncthreads();
        #pragma unroll
        for (int k = 0; k < 32; k++) {
            float a[4], b[4];
            #pragma unroll
            for (int i = 0; i < 4; i++) a[i] = sA[k][ty * 4 + i];
            #pragma unroll
            for (int j = 0; j < 4; j++) b[j] = sB[k][tx * 4 + j];
            #pragma unroll
            for (int i = 0; i < 4; i++)
                #pragma unroll
                for (int j = 0; j < 4; j++)
                    acc[i][j] = fmaf(a[i], b[j], acc[i][j]);
        }
        __syncthreads();
    }

    #pragma unroll
    for (int i = 0; i < 4; i++) {
        int m = m0 + ty * 4 + i;
        #pragma unroll
        for (int j = 0; j < 4; j++) {
            int n = n0 + tx * 4 + j;
            if (n < N) {
                float v = acc[i][j] + bias[n];
                if (ACT == 1) v = gelu_exact(v);
                if (ACT == 2) v += R[(size_t)m * N + n];
                C[(size_t)m * N + n] = v;
            }
        }
    }
}

// ---------------------------------------------------------------------------
// Phasor feature kernel: build real 128-dim features [Re(0..63) | Im(0..63)]
// periodic (j<48): exp(i * tanh(.)*pi), unit magnitude
// hyperbolic (j>=48): amp = 1-|z|, angle = atan2(z1, z0), z = tanh(.)*0.9
// ---------------------------------------------------------------------------
__global__ void feat_kernel(const float* __restrict__ kp, const float* __restrict__ qp,
                            const float* __restrict__ kh, const float* __restrict__ qh,
                            float* __restrict__ k2, float* __restrict__ q2)
{
    int row = blockIdx.x;     // 0..4095
    int j = threadIdx.x;      // 0..63
    float kre, kim, qre, qim;
    if (j < 48) {
        float a = tanhf(kp[row * 48 + j]) * PI_F;
        sincosf(a, &kim, &kre);
        a = tanhf(qp[row * 48 + j]) * PI_F;
        sincosf(a, &qim, &qre);
    } else {
        int jj = j - 48;
        float x0 = tanhf(kh[row * 32 + 2 * jj]) * 0.9f;
        float y0 = tanhf(kh[row * 32 + 2 * jj + 1]) * 0.9f;
        float ang = atan2f(y0, x0);
        float amp = 1.0f - sqrtf(x0 * x0 + y0 * y0);
        float s, c;
        sincosf(ang, &s, &c);
        kre = amp * c; kim = amp * s;
        x0 = tanhf(qh[row * 32 + 2 * jj]) * 0.9f;
        y0 = tanhf(qh[row * 32 + 2 * jj + 1]) * 0.9f;
        ang = atan2f(y0, x0);
        amp = 1.0f - sqrtf(x0 * x0 + y0 * y0);
        sincosf(ang, &s, &c);
        qre = amp * c; qim = amp * s;
    }
    k2[row * 128 + j] = kre; k2[row * 128 + 64 + j] = kim;
    q2[row * 128 + j] = qre; q2[row * 128 + 64 + j] = qim;
}

// ---------------------------------------------------------------------------
// Causal linear attention (no softmax):
//   ret[b,l,d] = (1/sqrt((l+1)*64)) * sum_{t<=l} (q2[b,l] . k2[b,t]) V[b,t,d]
// grid (16 qtiles, 2 d-splits, 4 batches), 256 threads.
// Q tile 64 rows; loop over kv tiles 0..qt; S in smem, O in registers.
// ---------------------------------------------------------------------------
#define SQT(k, r) smem[(k) * 68 + (r)]
#define SKT(k, r) smem[8704 + (k) * 68 + (r)]
#define SV(t, c)  smem[17408 + (t) * 128 + (c)]
#define SS(r, c)  smem[25600 + (r) * 65 + (c)]
#define ATTN_SMEM_FLOATS (8704 + 8704 + 8192 + 4160)
#define ATTN_SMEM_BYTES (ATTN_SMEM_FLOATS * 4)

__global__ void __launch_bounds__(256) attn_kernel(
    const float* __restrict__ Q2, const float* __restrict__ K2,
    const float* __restrict__ V, float* __restrict__ ret)
{
    extern __shared__ float smem[];
    const int tid = threadIdx.x;
    const int tx = tid & 15, ty = tid >> 4;
    const int qt = blockIdx.x;           // 0..15
    const int c0 = blockIdx.y * 128;     // d-split: 0 or 128
    const int b = blockIdx.z;
    const int qbase = b * 1024 + qt * 64;

    // load Q tile transposed: [feat][row]
    #pragma unroll
    for (int s = 0; s < 8; s++) {
        int slot = tid + s * 256;       // 0..2047
        int r = slot >> 5;              // 0..63
        int f = (slot & 31) << 2;       // 0..124
        float4 v = *(const float4*)&Q2[(size_t)(qbase + r) * 128 + f];
        SQT(f + 0, r) = v.x; SQT(f + 1, r) = v.y;
        SQT(f + 2, r) = v.z; SQT(f + 3, r) = v.w;
    }

    float acc[4][8];
    #pragma unroll
    for (int i = 0; i < 4; i++)
        #pragma unroll
        for (int c = 0; c < 8; c++) acc[i][c] = 0.f;

    for (int kt = 0; kt <= qt; kt++) {
        __syncthreads();   // prev iter reads of SKT/SV/SS done (also covers SQT on iter 0)
        const int kbase = b * 1024 + kt * 64;
        #pragma unroll
        for (int s = 0; s < 8; s++) {
            int slot = tid + s * 256;
            int r = slot >> 5;
            int f = (slot & 31) << 2;
            float4 v = *(const float4*)&K2[(size_t)(kbase + r) * 128 + f];
            SKT(f + 0, r) = v.x; SKT(f + 1, r) = v.y;
            SKT(f + 2, r) = v.z; SKT(f + 3, r) = v.w;
        }
        #pragma unroll
        for (int s = 0; s < 8; s++) {
            int slot = tid + s * 256;
            int r = slot >> 5;
            int c = (slot & 31) << 2;
            float4 v = *(const float4*)&V[(size_t)(kbase + r) * 256 + c0 + c];
            *(float4*)&SV(r, c) = v;
        }
        __syncthreads();

        // S = Qtile @ Ktile^T  (64x64), 4x4 per thread
        float sreg[4][4];
        #pragma unroll
        for (int i = 0; i < 4; i++)
            #pragma unroll
            for (int j = 0; j < 4; j++) sreg[i][j] = 0.f;

        #pragma unroll 8
        for (int k = 0; k < 128; k++) {
            float a[4], bb[4];
            #pragma unroll
            for (int i = 0; i < 4; i++) a[i] = SQT(k, ty * 4 + i);
            #pragma unroll
            for (int j = 0; j < 4; j++) bb[j] = SKT(k, tx * 4 + j);
            #pragma unroll
            for (int i = 0; i < 4; i++)
                #pragma unroll
                for (int j = 0; j < 4; j++)
                    sreg[i][j] = fmaf(a[i], bb[j], sreg[i][j]);
        }
        if (kt == qt) {  // causal mask (inclusive t<=l): zero where col > row
            #pragma unroll
            for (int i = 0; i < 4; i++)
                #pragma unroll
                for (int j = 0; j < 4; j++)
                    if (tx * 4 + j > ty * 4 + i) sreg[i][j] = 0.f;
        }
        #pragma unroll
        for (int i = 0; i < 4; i++)
            #pragma unroll
            for (int j = 0; j < 4; j++)
                SS(ty * 4 + i, tx * 4 + j) = sreg[i][j];
        __syncthreads();

        // O += S @ Vtile  (64 x 128 chunk); thread cols: 4tx..+3 and 64+4tx..+3
        #pragma unroll 4
        for (int t = 0; t < 64; t++) {
            float4 v0 = *(const float4*)&SV(t, tx * 4);
            float4 v1 = *(const float4*)&SV(t, 64 + tx * 4);
            #pragma unroll
            for (int i = 0; i < 4; i++) {
                float sv = SS(ty * 4 + i, t);
                acc[i][0] = fmaf(sv, v0.x, acc[i][0]);
                acc[i][1] = fmaf(sv, v0.y, acc[i][1]);
                acc[i][2] = fmaf(sv, v0.z, acc[i][2]);
                acc[i][3] = fmaf(sv, v0.w, acc[i][3]);
                acc[i][4] = fmaf(sv, v1.x, acc[i][4]);
                acc[i][5] = fmaf(sv, v1.y, acc[i][5]);
                acc[i][6] = fmaf(sv, v1.z, acc[i][6]);
                acc[i][7] = fmaf(sv, v1.w, acc[i][7]);
            }
        }
    }

    // epilogue: scale by 1/sqrt((l+1)*K), K=64
    #pragma unroll
    for (int i = 0; i < 4; i++) {
        int lr = ty * 4 + i;
        int grow = qbase + lr;
        float f = rsqrtf((float)(qt * 64 + lr + 1) * 64.0f);
        float4 o0 = make_float4(acc[i][0] * f, acc[i][1] * f, acc[i][2] * f, acc[i][3] * f);
        float4 o1 = make_float4(acc[i][4] * f, acc[i][5] * f, acc[i][6] * f, acc[i][7] * f);
        *(float4*)&ret[(size_t)grow * 256 + c0 + tx * 4] = o0;
        *(float4*)&ret[(size_t)grow * 256 + c0 + 64 + tx * 4] = o1;
    }
}

// ---------------------------------------------------------------------------
// LayerNorm over D=256 per row: one block/row, 256 threads.
// ---------------------------------------------------------------------------
__global__ void __launch_bounds__(256) ln_kernel(
    const float* __restrict__ ret, const float* __restrict__ g,
    const float* __restrict__ bta, float* __restrict__ out)
{
    int row = blockIdx.x;
    int t = threadIdx.x;
    float v = ret[(size_t)row * 256 + t];
    float s = v, s2 = v * v;
    #pragma unroll
    for (int o = 16; o > 0; o >>= 1) {
        s += __shfl_xor_sync(0xFFFFFFFFu, s, o);
        s2 += __shfl_xor_sync(0xFFFFFFFFu, s2, o);
    }
    __shared__ float ws[8], ws2[8];
    int w = t >> 5, ln = t & 31;
    if (ln == 0) { ws[w] = s; ws2[w] = s2; }
    __syncthreads();
    if (w == 0) {
        float a = (ln < 8) ? ws[ln] : 0.f;
        float a2 = (ln < 8) ? ws2[ln] : 0.f;
        #pragma unroll
        for (int o = 4; o > 0; o >>= 1) {
            a += __shfl_xor_sync(0xFFFFFFFFu, a, o);
            a2 += __shfl_xor_sync(0xFFFFFFFFu, a2, o);
        }
        if (ln == 0) { ws[0] = a; ws2[0] = a2; }
    }
    __syncthreads();
    float mean = ws[0] * (1.f / 256.f);
    float var = fmaxf(ws2[0] * (1.f / 256.f) - mean * mean, 0.f);
    out[(size_t)row * 256 + t] = (v - mean) * rsqrtf(var + 1e-5f) * g[t] + bta[t];
}

// ---------------------------------------------------------------------------
extern "C" void kernel_launch(void* const* d_in, const int* in_sizes, int n_in,
                              void* d_out, int out_size)
{
    (void)in_sizes; (void)n_in; (void)out_size;
    const float* x     = (const float*)d_in[0];
    const float* kp_w1 = (const float*)d_in[1];
    const float* kp_b1 = (const float*)d_in[2];
    const float* kp_w2 = (const float*)d_in[3];
    const float* kp_b2 = (const float*)d_in[4];
    const float* qp_w1 = (const float*)d_in[5];
    const float* qp_b1 = (const float*)d_in[6];
    const float* qp_w2 = (const float*)d_in[7];
    const float* qp_b2 = (const float*)d_in[8];
    const float* kh_w1 = (const float*)d_in[9];
    const float* kh_b1 = (const float*)d_in[10];
    const float* kh_w2 = (const float*)d_in[11];
    const float* kh_b2 = (const float*)d_in[12];
    const float* qh_w1 = (const float*)d_in[13];
    const float* qh_b1 = (const float*)d_in[14];
    const float* qh_w2 = (const float*)d_in[15];
    const float* qh_b2 = (const float*)d_in[16];
    const float* v_w   = (const float*)d_in[17];
    const float* v_b   = (const float*)d_in[18];
    const float* ln_g  = (const float*)d_in[19];
    const float* ln_b  = (const float*)d_in[20];
    const float* out_w = (const float*)d_in[21];
    const float* out_b = (const float*)d_in[22];
    float* out = (float*)d_out;

    float *hid, *kp, *qp, *kh, *qh, *k2, *q2, *V, *ret, *rln;
    cudaGetSymbolAddress((void**)&hid, g_hidden);
    cudaGetSymbolAddress((void**)&kp, g_kp);
    cudaGetSymbolAddress((void**)&qp, g_qp);
    cudaGetSymbolAddress((void**)&kh, g_kh);
    cudaGetSymbolAddress((void**)&qh, g_qh);
    cudaGetSymbolAddress((void**)&k2, g_k2);
    cudaGetSymbolAddress((void**)&q2, g_q2);
    cudaGetSymbolAddress((void**)&V, g_V);
    cudaGetSymbolAddress((void**)&ret, g_ret);
    cudaGetSymbolAddress((void**)&rln, g_rln);

    dim3 blk(256);
    dim3 gBig(64, 4);   // N=256
    dim3 gSm(64, 1);    // N=48/32

    // four MLPs (hidden buffer reused serially) + V projection
    gemm64<1><<<gBig, blk>>>(x, kp_w1, kp_b1, nullptr, hid, 256);
    gemm64<0><<<gSm, blk>>>(hid, kp_w2, kp_b2, nullptr, kp, 48);
    gemm64<1><<<gBig, blk>>>(x, qp_w1, qp_b1, nullptr, hid, 256);
    gemm64<0><<<gSm, blk>>>(hid, qp_w2, qp_b2, nullptr, qp, 48);
    gemm64<1><<<gBig, blk>>>(x, kh_w1, kh_b1, nullptr, hid, 256);
    gemm64<0><<<gSm, blk>>>(hid, kh_w2, kh_b2, nullptr, kh, 32);
    gemm64<1><<<gBig, blk>>>(x, qh_w1, qh_b1, nullptr, hid, 256);
    gemm64<0><<<gSm, blk>>>(hid, qh_w2, qh_b2, nullptr, qh, 32);
    gemm64<0><<<gBig, blk>>>(x, v_w, v_b, nullptr, V, 256);

    // phasor features (B*L rows, 64 oscillators each)
    feat_kernel<<<4096, 64>>>(kp, qp, kh, qh, k2, q2);

    // causal linear attention
    cudaFuncSetAttribute(attn_kernel, cudaFuncAttributeMaxDynamicSharedMemorySize,
                         ATTN_SMEM_BYTES);
    attn_kernel<<<dim3(16, 2, 4), blk, ATTN_SMEM_BYTES>>>(q2, k2, V, ret);

    // LayerNorm then output projection with residual
    ln_kernel<<<4096, blk>>>(ret, ln_g, ln_b, rln);
    gemm64<2><<<gBig, blk>>>(rln, out_w, out_b, x, out, 256);
}

// round 2
// speedup vs baseline: 1.5836x; 1.5836x over previous
#include <cuda_runtime.h>
#include <math.h>

// B=4, L=1024, D=256, N_PER=48, N_HYP=16, K=64, features 2K=128
#define M_ROWS 4096
#define LDH 1280
#define PI_F 3.14159265358979323846f

// scratch
__device__ float g_hid[M_ROWS * LDH];   // [GELU(kp|qp|kh|qh hidden) | V]
__device__ float g_k2[M_ROWS * 128];
__device__ float g_q2[M_ROWS * 128];
__device__ float g_ret[M_ROWS * 256];   // low-half partial / full
__device__ float g_ret2[M_ROWS * 256];  // high-half partial (qt>=8 rows only)
__device__ float g_rln[M_ROWS * 256];

__device__ __forceinline__ float gelu_exact(float v) {
    return 0.5f * v * (1.0f + erff(v * 0.7071067811865475f));
}

// ---------------------------------------------------------------------------
// 128x64 fp32 tile engine: acc[8][4] += A[128,256](lda) @ W[64,256]^T
// sA stride 132 (conflict-free-ish transposed stores, 16B-aligned reads),
// sB stride 68. 256 threads, 8x4 microtile.
// ---------------------------------------------------------------------------
template <bool GUARD>
__device__ __forceinline__ void tile128x64(
    const float* __restrict__ A, int lda,
    const float* __restrict__ W, int nvalid,
    float* sA, float* sB, float acc[8][4])
{
    const int tid = threadIdx.x;
    const int tx = tid & 15, ty = tid >> 4;

    for (int k0 = 0; k0 < 256; k0 += 32) {
        #pragma unroll
        for (int s = 0; s < 4; s++) {          // A: 128x32
            int slot = tid + s * 256;           // 0..1023
            int r = slot >> 3;                  // 0..127
            int kk = (slot & 7) << 2;           // 0..28
            float4 va = *(const float4*)&A[(size_t)r * lda + k0 + kk];
            sA[(kk + 0) * 132 + r] = va.x;
            sA[(kk + 1) * 132 + r] = va.y;
            sA[(kk + 2) * 132 + r] = va.z;
            sA[(kk + 3) * 132 + r] = va.w;
        }
        #pragma unroll
        for (int s = 0; s < 2; s++) {          // W: 64x32
            int slot = tid + s * 256;           // 0..511
            int r = slot >> 3;                  // 0..63
            int kk = (slot & 7) << 2;
            float4 vw = make_float4(0.f, 0.f, 0.f, 0.f);
            if (!GUARD || r < nvalid)
                vw = *(const float4*)&W[(size_t)r * 256 + k0 + kk];
            sB[(kk + 0) * 68 + r] = vw.x;
            sB[(kk + 1) * 68 + r] = vw.y;
            sB[(kk + 2) * 68 + r] = vw.z;
            sB[(kk + 3) * 68 + r] = vw.w;
        }
        __syncthreads();
        #pragma unroll 16
        for (int k = 0; k < 32; k++) {
            float4 a0 = *(const float4*)&sA[k * 132 + ty * 8];
            float4 a1 = *(const float4*)&sA[k * 132 + ty * 8 + 4];
            float4 bv = *(const float4*)&sB[k * 68 + tx * 4];
            float aa[8] = {a0.x, a0.y, a0.z, a0.w, a1.x, a1.y, a1.z, a1.w};
            float bb[4] = {bv.x, bv.y, bv.z, bv.w};
            #pragma unroll
            for (int i = 0; i < 8; i++)
                #pragma unroll
                for (int j = 0; j < 4; j++)
                    acc[i][j] = fmaf(aa[i], bb[j], acc[i][j]);
        }
        __syncthreads();
    }
}

// ---------------------------------------------------------------------------
// Fused first layers: hid[4096,1280] = [GELU(x@W1^T+b1) x4 | x@v_w^T+v_b]
// grid (32, 20)
// ---------------------------------------------------------------------------
__global__ void __launch_bounds__(256) gemm_fused1(
    const float* __restrict__ x,
    const float* __restrict__ w0, const float* __restrict__ b0,
    const float* __restrict__ w1, const float* __restrict__ b1,
    const float* __restrict__ w2, const float* __restrict__ b2,
    const float* __restrict__ w3, const float* __restrict__ b3,
    const float* __restrict__ w4, const float* __restrict__ b4,
    float* __restrict__ hid)
{
    __shared__ float sA[32 * 132];
    __shared__ float sB[32 * 68];
    const int tid = threadIdx.x;
    const int tx = tid & 15, ty = tid >> 4;
    const int m0 = blockIdx.x * 128;
    const int by = blockIdx.y;
    const int seg = by >> 2;
    const int wrow = (by & 3) * 64;

    const float* W; const float* Bs;
    if      (seg == 0) { W = w0; Bs = b0; }
    else if (seg == 1) { W = w1; Bs = b1; }
    else if (seg == 2) { W = w2; Bs = b2; }
    else if (seg == 3) { W = w3; Bs = b3; }
    else               { W = w4; Bs = b4; }
    W += (size_t)wrow * 256;

    float acc[8][4] = {};
    tile128x64<false>(x + (size_t)m0 * 256, 256, W, 64, sA, sB, acc);

    const int ncol0 = by * 64 + tx * 4;
    #pragma unroll
    for (int i = 0; i < 8; i++) {
        int m = m0 + ty * 8 + i;
        float4 o;
        float* po = &o.x;
        #pragma unroll
        for (int j = 0; j < 4; j++) {
            float v = acc[i][j] + Bs[wrow + tx * 4 + j];
            if (seg < 4) v = gelu_exact(v);
            po[j] = v;
        }
        *(float4*)&hid[(size_t)m * LDH + ncol0] = o;
    }
}

// ---------------------------------------------------------------------------
// Fused second layers + phasor features: writes k2/q2 [4096,128] directly.
// grid (32, 4): seg 0=kp->k2 per, 1=qp->q2 per, 2=kh->k2 hyp, 3=qh->q2 hyp
// feature layout: [per re 0..47 | hyp re 48..63 | per im 64..111 | hyp im 112..127]
// ---------------------------------------------------------------------------
__global__ void __launch_bounds__(256) layer2_feat(
    const float* __restrict__ hid,
    const float* __restrict__ w0, const float* __restrict__ b0,
    const float* __restrict__ w1, const float* __restrict__ b1,
    const float* __restrict__ w2, const float* __restrict__ b2,
    const float* __restrict__ w3, const float* __restrict__ b3,
    float* __restrict__ k2, float* __restrict__ q2)
{
    __shared__ float sA[32 * 132];
    __shared__ float sB[32 * 68];
    const int tid = threadIdx.x;
    const int tx = tid & 15, ty = tid >> 4;
    const int m0 = blockIdx.x * 128;
    const int seg = blockIdx.y;

    const float* W; const float* Bs;
    if      (seg == 0) { W = w0; Bs = b0; }
    else if (seg == 1) { W = w1; Bs = b1; }
    else if (seg == 2) { W = w2; Bs = b2; }
    else               { W = w3; Bs = b3; }
    const int nseg = (seg < 2) ? 48 : 32;

    float acc[8][4] = {};
    tile128x64<true>(hid + (size_t)m0 * LDH + seg * 256, LDH, W, nseg, sA, sB, acc);

    float* dst = (seg == 0 || seg == 2) ? k2 : q2;

    if (seg < 2) {
        // periodic: phasor = exp(i * tanh(y)*pi)
        #pragma unroll
        for (int i = 0; i < 8; i++) {
            int m = m0 + ty * 8 + i;
            #pragma unroll
            for (int j = 0; j < 4; j++) {
                int n = tx * 4 + j;
                if (n < 48) {
                    float ang = tanhf(acc[i][j] + Bs[n]) * PI_F;
                    float s, c;
                    sincosf(ang, &s, &c);
                    dst[(size_t)m * 128 + n] = c;
                    dst[(size_t)m * 128 + 64 + n] = s;
                }
            }
        }
    } else {
        // hyperbolic: z = tanh(y)*0.9 pairs; phasor = (1-|z|) * z/|z|
        if (tx < 8) {
            #pragma unroll
            for (int i = 0; i < 8; i++) {
                int m = m0 + ty * 8 + i;
                #pragma unroll
                for (int p = 0; p < 2; p++) {
                    float x0 = tanhf(acc[i][2 * p + 0] + Bs[tx * 4 + 2 * p + 0]) * 0.9f;
                    float y0 = tanhf(acc[i][2 * p + 1] + Bs[tx * 4 + 2 * p + 1]) * 0.9f;
                    float r = sqrtf(x0 * x0 + y0 * y0);
                    float re, im;
                    if (r > 0.0f) {
                        float s = (1.0f - r) / r;
                        re = x0 * s; im = y0 * s;
                    } else { re = 1.0f; im = 0.0f; }
                    int jj = tx * 2 + p;
                    dst[(size_t)m * 128 + 48 + jj] = re;
                    dst[(size_t)m * 128 + 112 + jj] = im;
                }
            }
        }
    }
}

// ---------------------------------------------------------------------------
// Balanced causal linear attention.
// items: (qt, kv_lo, kv_hi); qt>=8 split in two halves. lo==0 -> g_ret,
// lo>0 -> g_ret2 (summed in LN for rows l>=512). Plain stores, no atomics.
// grid (24 items, 2 d-splits, 4 batches), 256 threads, dyn smem.
// ---------------------------------------------------------------------------
__constant__ int c_item[24][3] = {
    {15, 0, 8}, {15, 8, 16}, {14, 7, 15}, {7, 0, 8},
    {14, 0, 7}, {13, 0, 7},  {13, 7, 14}, {12, 6, 13}, {6, 0, 7},
    {12, 0, 6}, {11, 0, 6},  {11, 6, 12}, {10, 5, 11}, {5, 0, 6},
    {10, 0, 5}, {9, 0, 5},   {9, 5, 10},  {8, 4, 9},   {4, 0, 5},
    {8, 0, 4},  {3, 0, 4},   {2, 0, 3},   {1, 0, 2},   {0, 0, 1}
};

#define SQT(k, r) smem[(k) * 68 + (r)]
#define SKT(k, r) smem[8704 + (k) * 68 + (r)]
#define SV(t, c)  smem[17408 + (t) * 128 + (c)]
#define SS(r, c)  smem[25600 + (r) * 68 + (c)]
#define ATTN_SMEM_BYTES ((25600 + 64 * 68) * 4)

__global__ void __launch_bounds__(256) attn_kernel(
    const float* __restrict__ Q2, const float* __restrict__ K2,
    const float* __restrict__ Vb,   // hid + 1024, row stride LDH
    float* __restrict__ ret, float* __restrict__ ret2)
{
    extern __shared__ float smem[];
    const int tid = threadIdx.x;
    const int tx = tid & 15, ty = tid >> 4;
    const int qt = c_item[blockIdx.x][0];
    const int lo = c_item[blockIdx.x][1];
    const int hi = c_item[blockIdx.x][2];
    const int c0 = blockIdx.y * 128;
    const int b = blockIdx.z;
    const int qbase = b * 1024 + qt * 64;

    // Q tile transposed [feat][row]
    #pragma unroll
    for (int s = 0; s < 8; s++) {
        int slot = tid + s * 256;
        int r = slot >> 5;
        int f = (slot & 31) << 2;
        float4 v = *(const float4*)&Q2[(size_t)(qbase + r) * 128 + f];
        SQT(f + 0, r) = v.x; SQT(f + 1, r) = v.y;
        SQT(f + 2, r) = v.z; SQT(f + 3, r) = v.w;
    }

    float acc[4][8];
    #pragma unroll
    for (int i = 0; i < 4; i++)
        #pragma unroll
        for (int c = 0; c < 8; c++) acc[i][c] = 0.f;

    for (int kt = lo; kt < hi; kt++) {
        __syncthreads();
        const int kbase = b * 1024 + kt * 64;
        #pragma unroll
        for (int s = 0; s < 8; s++) {
            int slot = tid + s * 256;
            int r = slot >> 5;
            int f = (slot & 31) << 2;
            float4 v = *(const float4*)&K2[(size_t)(kbase + r) * 128 + f];
            SKT(f + 0, r) = v.x; SKT(f + 1, r) = v.y;
            SKT(f + 2, r) = v.z; SKT(f + 3, r) = v.w;
        }
        #pragma unroll
        for (int s = 0; s < 8; s++) {
            int slot = tid + s * 256;
            int r = slot >> 5;
            int c = (slot & 31) << 2;
            float4 v = *(const float4*)&Vb[(size_t)(kbase + r) * LDH + c0 + c];
            *(float4*)&SV(r, c) = v;
        }
        __syncthreads();

        // S = Qtile @ Ktile^T (64x64)
        float sreg[4][4];
        #pragma unroll
        for (int i = 0; i < 4; i++)
            #pragma unroll
            for (int j = 0; j < 4; j++) sreg[i][j] = 0.f;

        #pragma unroll 8
        for (int k = 0; k < 128; k++) {
            float4 av = *(const float4*)&SQT(k, ty * 4);
            float4 bv = *(const float4*)&SKT(k, tx * 4);
            float a[4] = {av.x, av.y, av.z, av.w};
            float bb[4] = {bv.x, bv.y, bv.z, bv.w};
            #pragma unroll
            for (int i = 0; i < 4; i++)
                #pragma unroll
                for (int j = 0; j < 4; j++)
                    sreg[i][j] = fmaf(a[i], bb[j], sreg[i][j]);
        }
        if (kt == qt) {  // inclusive causal mask
            #pragma unroll
            for (int i = 0; i < 4; i++)
                #pragma unroll
                for (int j = 0; j < 4; j++)
                    if (tx * 4 + j > ty * 4 + i) sreg[i][j] = 0.f;
        }
        #pragma unroll
        for (int i = 0; i < 4; i++)
            *(float4*)&SS(ty * 4 + i, tx * 4) =
                make_float4(sreg[i][0], sreg[i][1], sreg[i][2], sreg[i][3]);
        __syncthreads();

        // O += S @ Vtile (64 x 128)
        #pragma unroll 4
        for (int t = 0; t < 64; t++) {
            float4 v0 = *(const float4*)&SV(t, tx * 4);
            float4 v1 = *(const float4*)&SV(t, 64 + tx * 4);
            #pragma unroll
            for (int i = 0; i < 4; i++) {
                float sv = SS(ty * 4 + i, t);
                acc[i][0] = fmaf(sv, v0.x, acc[i][0]);
                acc[i][1] = fmaf(sv, v0.y, acc[i][1]);
                acc[i][2] = fmaf(sv, v0.z, acc[i][2]);
                acc[i][3] = fmaf(sv, v0.w, acc[i][3]);
                acc[i][4] = fmaf(sv, v1.x, acc[i][4]);
                acc[i][5] = fmaf(sv, v1.y, acc[i][5]);
                acc[i][6] = fmaf(sv, v1.z, acc[i][6]);
                acc[i][7] = fmaf(sv, v1.w, acc[i][7]);
            }
        }
    }

    float* dst = (lo == 0) ? ret : ret2;
    #pragma unroll
    for (int i = 0; i < 4; i++) {
        int grow = qbase + ty * 4 + i;
        *(float4*)&dst[(size_t)grow * 256 + c0 + tx * 4] =
            make_float4(acc[i][0], acc[i][1], acc[i][2], acc[i][3]);
        *(float4*)&dst[(size_t)grow * 256 + c0 + 64 + tx * 4] =
            make_float4(acc[i][4], acc[i][5], acc[i][6], acc[i][7]);
    }
}

// ---------------------------------------------------------------------------
// partial-sum + position scale + LayerNorm. one block/row, 256 threads.
// ---------------------------------------------------------------------------
__global__ void __launch_bounds__(256) ln_kernel(
    const float* __restrict__ ret, const float* __restrict__ ret2,
    const float* __restrict__ g, const float* __restrict__ bta,
    float* __restrict__ out)
{
    int row = blockIdx.x;
    int t = threadIdx.x;
    int l = row & 1023;
    float v = ret[(size_t)row * 256 + t];
    if (l >= 512) v += ret2[(size_t)row * 256 + t];
    v *= rsqrtf((float)(l + 1) * 64.0f);

    float s = v, s2 = v * v;
    #pragma unroll
    for (int o = 16; o > 0; o >>= 1) {
        s += __shfl_xor_sync(0xFFFFFFFFu, s, o);
        s2 += __shfl_xor_sync(0xFFFFFFFFu, s2, o);
    }
    __shared__ float ws[8], ws2[8];
    int w = t >> 5, ln = t & 31;
    if (ln == 0) { ws[w] = s; ws2[w] = s2; }
    __syncthreads();
    if (w == 0) {
        float a = (ln < 8) ? ws[ln] : 0.f;
        float a2 = (ln < 8) ? ws2[ln] : 0.f;
        #pragma unroll
        for (int o = 4; o > 0; o >>= 1) {
            a += __shfl_xor_sync(0xFFFFFFFFu, a, o);
            a2 += __shfl_xor_sync(0xFFFFFFFFu, a2, o);
        }
        if (ln == 0) { ws[0] = a; ws2[0] = a2; }
    }
    __syncthreads();
    float mean = ws[0] * (1.f / 256.f);
    float var = fmaxf(ws2[0] * (1.f / 256.f) - mean * mean, 0.f);
    out[(size_t)row * 256 + t] = (v - mean) * rsqrtf(var + 1e-5f) * g[t] + bta[t];
}

// ---------------------------------------------------------------------------
// out = x + rln @ out_w^T + out_b.  grid (32, 4).
// ---------------------------------------------------------------------------
__global__ void __launch_bounds__(256) gemm_out(
    const float* __restrict__ rln, const float* __restrict__ W,
    const float* __restrict__ Bs, const float* __restrict__ x,
    float* __restrict__ out)
{
    __shared__ float sA[32 * 132];
    __shared__ float sB[32 * 68];
    const int tid = threadIdx.x;
    const int tx = tid & 15, ty = tid >> 4;
    const int m0 = blockIdx.x * 128;
    const int n0 = blockIdx.y * 64;

    float acc[8][4] = {};
    tile128x64<false>(rln + (size_t)m0 * 256, 256, W + (size_t)n0 * 256, 64, sA, sB, acc);

    #pragma unroll
    for (int i = 0; i < 8; i++) {
        int m = m0 + ty * 8 + i;
        int n = n0 + tx * 4;
        float4 r = *(const float4*)&x[(size_t)m * 256 + n];
        float4 o;
        o.x = acc[i][0] + Bs[n + 0] + r.x;
        o.y = acc[i][1] + Bs[n + 1] + r.y;
        o.z = acc[i][2] + Bs[n + 2] + r.z;
        o.w = acc[i][3] + Bs[n + 3] + r.w;
        *(float4*)&out[(size_t)m * 256 + n] = o;
    }
}

// ---------------------------------------------------------------------------
extern "C" void kernel_launch(void* const* d_in, const int* in_sizes, int n_in,
                              void* d_out, int out_size)
{
    (void)in_sizes; (void)n_in; (void)out_size;
    const float* x     = (const float*)d_in[0];
    const float* kp_w1 = (const float*)d_in[1];
    const float* kp_b1 = (const float*)d_in[2];
    const float* kp_w2 = (const float*)d_in[3];
    const float* kp_b2 = (const float*)d_in[4];
    const float* qp_w1 = (const float*)d_in[5];
    const float* qp_b1 = (const float*)d_in[6];
    const float* qp_w2 = (const float*)d_in[7];
    const float* qp_b2 = (const float*)d_in[8];
    const float* kh_w1 = (const float*)d_in[9];
    const float* kh_b1 = (const float*)d_in[10];
    const float* kh_w2 = (const float*)d_in[11];
    const float* kh_b2 = (const float*)d_in[12];
    const float* qh_w1 = (const float*)d_in[13];
    const float* qh_b1 = (const float*)d_in[14];
    const float* qh_w2 = (const float*)d_in[15];
    const float* qh_b2 = (const float*)d_in[16];
    const float* v_w   = (const float*)d_in[17];
    const float* v_b   = (const float*)d_in[18];
    const float* ln_g  = (const float*)d_in[19];
    const float* ln_b  = (const float*)d_in[20];
    const float* out_w = (const float*)d_in[21];
    const float* out_b = (const float*)d_in[22];
    float* out = (float*)d_out;

    float *hid, *k2, *q2, *ret, *ret2, *rln;
    cudaGetSymbolAddress((void**)&hid, g_hid);
    cudaGetSymbolAddress((void**)&k2, g_k2);
    cudaGetSymbolAddress((void**)&q2, g_q2);
    cudaGetSymbolAddress((void**)&ret, g_ret);
    cudaGetSymbolAddress((void**)&ret2, g_ret2);
    cudaGetSymbolAddress((void**)&rln, g_rln);

    dim3 blk(256);

    // 1. fused first layers + V projection
    gemm_fused1<<<dim3(32, 20), blk>>>(x, kp_w1, kp_b1, qp_w1, qp_b1,
                                       kh_w1, kh_b1, qh_w1, qh_b1,
                                       v_w, v_b, hid);

    // 2. fused second layers -> phasor features
    layer2_feat<<<dim3(32, 4), blk>>>(hid, kp_w2, kp_b2, qp_w2, qp_b2,
                                      kh_w2, kh_b2, qh_w2, qh_b2, k2, q2);

    // 3. balanced causal linear attention
    static bool attr_set = false;
    if (!attr_set) {
        cudaFuncSetAttribute(attn_kernel, cudaFuncAttributeMaxDynamicSharedMemorySize,
                             ATTN_SMEM_BYTES);
        attr_set = true;
    }
    attn_kernel<<<dim3(24, 2, 4), blk, ATTN_SMEM_BYTES>>>(q2, k2, hid + 1024, ret, ret2);

    // 4. partial-sum + scale + LayerNorm
    ln_kernel<<<4096, blk>>>(ret, ret2, ln_g, ln_b, rln);

    // 5. output projection + residual
    gemm_out<<<dim3(32, 4), blk>>>(rln, out_w, out_b, x, out);
}

// round 3
// speedup vs baseline: 3.8800x; 2.4501x over previous
#include <cuda_runtime.h>
#include <math.h>
#include <stdint.h>

// B=4, L=1024, D=256, N_PER=48, N_HYP=16, K=64, features 2K=128
#define M_ROWS 4096
#define LDH 1280
#define PI_F 3.14159265358979323846f
#define TA_LD 36   // smem k-chunk stride (36 mod 32 = 4 -> conflict-free frags)

// scratch
__device__ float g_hid[M_ROWS * LDH];   // [GELU(kp|qp|kh|qh hidden) | V]
__device__ float g_k2[M_ROWS * 128];
__device__ float g_q2[M_ROWS * 128];
__device__ float g_ret[M_ROWS * 256];
__device__ float g_ret2[M_ROWS * 256];
__device__ float g_rln[M_ROWS * 256];

__device__ __forceinline__ float gelu_exact(float v) {
    return 0.5f * v * (1.0f + erff(v * 0.7071067811865475f));
}

__device__ __forceinline__ uint32_t f2t(float f) {
    uint32_t u;
    asm("cvt.rna.tf32.f32 %0, %1;" : "=r"(u) : "f"(f));
    return u;
}

__device__ __forceinline__ void mma8(float c[4], const uint32_t a[4], const uint32_t b[2]) {
    asm("mma.sync.aligned.m16n8k8.row.col.f32.tf32.tf32.f32 "
        "{%0,%1,%2,%3},{%4,%5,%6,%7},{%8,%9},{%0,%1,%2,%3};"
        : "+f"(c[0]), "+f"(c[1]), "+f"(c[2]), "+f"(c[3])
        : "r"(a[0]), "r"(a[1]), "r"(a[2]), "r"(a[3]), "r"(b[0]), "r"(b[1]));
}

// ---------------------------------------------------------------------------
// 128x64 TF32 MMA tile engine: acc += A[128,256](lda) @ W[64,256]^T
// 256 threads = 8 warps in 4(m) x 2(n) grid, warp tile 32x32.
// acc[mf][nf][{c0..c3}]: c0=(g,2t) c1=(g,2t+1) c2=(g+8,2t) c3=(g+8,2t+1)
// ---------------------------------------------------------------------------
template <bool GUARD>
__device__ __forceinline__ void tile_mma(
    const float* __restrict__ A, int lda,
    const float* __restrict__ W, int nvalid,
    uint32_t* sA, uint32_t* sB, float acc[2][4][4],
    int warpM, int warpN, int group, int tig)
{
    const int tid = threadIdx.x;
    for (int k0 = 0; k0 < 256; k0 += 32) {
        #pragma unroll
        for (int s = 0; s < 4; s++) {           // A: 128 x 32
            int slot = tid + s * 256;
            int r = slot >> 3;
            int kk = (slot & 7) << 2;
            float4 v = *(const float4*)&A[(size_t)r * lda + k0 + kk];
            uint4 u;
            u.x = f2t(v.x); u.y = f2t(v.y); u.z = f2t(v.z); u.w = f2t(v.w);
            *(uint4*)&sA[r * TA_LD + kk] = u;
        }
        #pragma unroll
        for (int s = 0; s < 2; s++) {           // W: 64 x 32
            int slot = tid + s * 256;
            int r = slot >> 3;
            int kk = (slot & 7) << 2;
            uint4 u = make_uint4(0u, 0u, 0u, 0u);
            if (!GUARD || r < nvalid) {
                float4 v = *(const float4*)&W[(size_t)r * 256 + k0 + kk];
                u.x = f2t(v.x); u.y = f2t(v.y); u.z = f2t(v.z); u.w = f2t(v.w);
            }
            *(uint4*)&sB[r * TA_LD + kk] = u;
        }
        __syncthreads();
        #pragma unroll
        for (int ks = 0; ks < 4; ks++) {
            int kb = ks * 8;
            uint32_t a[2][4], b[4][2];
            #pragma unroll
            for (int mf = 0; mf < 2; mf++) {
                int r0 = warpM * 32 + mf * 16 + group;
                a[mf][0] = sA[r0 * TA_LD + kb + tig];
                a[mf][1] = sA[(r0 + 8) * TA_LD + kb + tig];
                a[mf][2] = sA[r0 * TA_LD + kb + tig + 4];
                a[mf][3] = sA[(r0 + 8) * TA_LD + kb + tig + 4];
            }
            #pragma unroll
            for (int nf = 0; nf < 4; nf++) {
                int n0 = warpN * 32 + nf * 8 + group;
                b[nf][0] = sB[n0 * TA_LD + kb + tig];
                b[nf][1] = sB[n0 * TA_LD + kb + tig + 4];
            }
            #pragma unroll
            for (int mf = 0; mf < 2; mf++)
                #pragma unroll
                for (int nf = 0; nf < 4; nf++)
                    mma8(acc[mf][nf], a[mf], b[nf]);
        }
        __syncthreads();
    }
}

// ---------------------------------------------------------------------------
// Fused first layers: hid[4096,1280] = [GELU(x@W1^T+b1) x4 | x@v_w^T+v_b]
// grid (32, 20)
// ---------------------------------------------------------------------------
__global__ void __launch_bounds__(256) gemm_fused1(
    const float* __restrict__ x,
    const float* __restrict__ w0, const float* __restrict__ b0,
    const float* __restrict__ w1, const float* __restrict__ b1,
    const float* __restrict__ w2, const float* __restrict__ b2,
    const float* __restrict__ w3, const float* __restrict__ b3,
    const float* __restrict__ w4, const float* __restrict__ b4,
    float* __restrict__ hid)
{
    __shared__ uint32_t sA[128 * TA_LD];
    __shared__ uint32_t sB[64 * TA_LD];
    const int tid = threadIdx.x, lane = tid & 31, wid = tid >> 5;
    const int group = lane >> 2, tig = lane & 3;
    const int warpM = wid & 3, warpN = wid >> 2;
    const int m0 = blockIdx.x * 128;
    const int by = blockIdx.y;
    const int seg = by >> 2;
    const int wrow = (by & 3) * 64;

    const float* W; const float* Bs;
    if      (seg == 0) { W = w0; Bs = b0; }
    else if (seg == 1) { W = w1; Bs = b1; }
    else if (seg == 2) { W = w2; Bs = b2; }
    else if (seg == 3) { W = w3; Bs = b3; }
    else               { W = w4; Bs = b4; }
    W += (size_t)wrow * 256;

    float acc[2][4][4] = {};
    tile_mma<false>(x + (size_t)m0 * 256, 256, W, 64, sA, sB, acc,
                    warpM, warpN, group, tig);

    #pragma unroll
    for (int mf = 0; mf < 2; mf++) {
        int r0 = m0 + warpM * 32 + mf * 16 + group;
        #pragma unroll
        for (int nf = 0; nf < 4; nf++) {
            int colL = warpN * 32 + nf * 8 + 2 * tig;
            float bv0 = Bs[wrow + colL], bv1 = Bs[wrow + colL + 1];
            float v00 = acc[mf][nf][0] + bv0, v01 = acc[mf][nf][1] + bv1;
            float v10 = acc[mf][nf][2] + bv0, v11 = acc[mf][nf][3] + bv1;
            if (seg < 4) {
                v00 = gelu_exact(v00); v01 = gelu_exact(v01);
                v10 = gelu_exact(v10); v11 = gelu_exact(v11);
            }
            *(float2*)&hid[(size_t)r0 * LDH + by * 64 + colL] = make_float2(v00, v01);
            *(float2*)&hid[(size_t)(r0 + 8) * LDH + by * 64 + colL] = make_float2(v10, v11);
        }
    }
}

// ---------------------------------------------------------------------------
// Fused second layers + phasor features -> k2/q2 [4096,128].
// grid (32, 4): seg 0=kp->k2 per, 1=qp->q2 per, 2=kh->k2 hyp, 3=qh->q2 hyp
// feature layout: [per re 0..47 | hyp re 48..63 | per im 64..111 | hyp im 112..127]
// ---------------------------------------------------------------------------
__global__ void __launch_bounds__(256) layer2_feat(
    const float* __restrict__ hid,
    const float* __restrict__ w0, const float* __restrict__ b0,
    const float* __restrict__ w1, const float* __restrict__ b1,
    const float* __restrict__ w2, const float* __restrict__ b2,
    const float* __restrict__ w3, const float* __restrict__ b3,
    float* __restrict__ k2, float* __restrict__ q2)
{
    __shared__ uint32_t sA[128 * TA_LD];
    __shared__ uint32_t sB[64 * TA_LD];
    const int tid = threadIdx.x, lane = tid & 31, wid = tid >> 5;
    const int group = lane >> 2, tig = lane & 3;
    const int warpM = wid & 3, warpN = wid >> 2;
    const int m0 = blockIdx.x * 128;
    const int seg = blockIdx.y;

    const float* W; const float* Bs;
    if      (seg == 0) { W = w0; Bs = b0; }
    else if (seg == 1) { W = w1; Bs = b1; }
    else if (seg == 2) { W = w2; Bs = b2; }
    else               { W = w3; Bs = b3; }
    const int nseg = (seg < 2) ? 48 : 32;

    float acc[2][4][4] = {};
    tile_mma<true>(hid + (size_t)m0 * LDH + seg * 256, LDH, W, nseg, sA, sB, acc,
                   warpM, warpN, group, tig);

    float* dst = (seg == 0 || seg == 2) ? k2 : q2;

    if (seg < 2) {
        #pragma unroll
        for (int mf = 0; mf < 2; mf++) {
            int r0 = m0 + warpM * 32 + mf * 16 + group;
            #pragma unroll
            for (int nf = 0; nf < 4; nf++) {
                int colL = warpN * 32 + nf * 8 + 2 * tig;
                #pragma unroll
                for (int e = 0; e < 4; e++) {
                    int n = colL + (e & 1);
                    int m = (e < 2) ? r0 : r0 + 8;
                    if (n < 48) {
                        float ang = tanhf(acc[mf][nf][e] + Bs[n]) * PI_F;
                        float s, c;
                        sincosf(ang, &s, &c);
                        dst[(size_t)m * 128 + n] = c;
                        dst[(size_t)m * 128 + 64 + n] = s;
                    }
                }
            }
        }
    } else {
        #pragma unroll
        for (int mf = 0; mf < 2; mf++) {
            int r0 = m0 + warpM * 32 + mf * 16 + group;
            #pragma unroll
            for (int nf = 0; nf < 4; nf++) {
                int colL = warpN * 32 + nf * 8 + 2 * tig;
                if (colL < 32) {
                    int jj = colL >> 1;
                    float B0 = Bs[colL], B1 = Bs[colL + 1];
                    #pragma unroll
                    for (int h = 0; h < 2; h++) {
                        int m = (h == 0) ? r0 : r0 + 8;
                        float x0 = tanhf(acc[mf][nf][2 * h + 0] + B0) * 0.9f;
                        float y0 = tanhf(acc[mf][nf][2 * h + 1] + B1) * 0.9f;
                        float r = sqrtf(x0 * x0 + y0 * y0);
                        float re, im;
                        if (r > 0.0f) {
                            float sc = (1.0f - r) / r;
                            re = x0 * sc; im = y0 * sc;
                        } else { re = 1.0f; im = 0.0f; }
                        dst[(size_t)m * 128 + 48 + jj] = re;
                        dst[(size_t)m * 128 + 112 + jj] = im;
                    }
                }
            }
        }
    }
}

// ---------------------------------------------------------------------------
// Balanced causal linear attention, TF32 MMA.
// items: (qt, kv_lo, kv_hi); qt>=8 split. lo==0 -> ret else ret2.
// grid (24 items, 2 d-splits, 4 batches), 256 threads.
// ---------------------------------------------------------------------------
__constant__ int c_item[24][3] = {
    {15, 0, 8}, {15, 8, 16}, {14, 7, 15}, {7, 0, 8},
    {14, 0, 7}, {13, 0, 7},  {13, 7, 14}, {12, 6, 13}, {6, 0, 7},
    {12, 0, 6}, {11, 0, 6},  {11, 6, 12}, {10, 5, 11}, {5, 0, 6},
    {10, 0, 5}, {9, 0, 5},   {9, 5, 10},  {8, 4, 9},   {4, 0, 5},
    {8, 0, 4},  {3, 0, 4},   {2, 0, 3},   {1, 0, 2},   {0, 0, 1}
};

// smem (uint32 units): sQ[64*132] sK[64*132] sV[64*136] sS[64*68]
#define ATTN_SMEM_U32 (8448 + 8448 + 8704 + 4352)
#define ATTN_SMEM_BYTES (ATTN_SMEM_U32 * 4)

__global__ void __launch_bounds__(256) attn_kernel(
    const float* __restrict__ Q2, const float* __restrict__ K2,
    const float* __restrict__ Vb,   // hid + 1024, row stride LDH
    float* __restrict__ ret, float* __restrict__ ret2)
{
    extern __shared__ uint32_t smu[];
    uint32_t* sQ = smu;
    uint32_t* sK = smu + 8448;
    uint32_t* sV = smu + 16896;
    uint32_t* sS = smu + 25600;

    const int tid = threadIdx.x, lane = tid & 31, wid = tid >> 5;
    const int group = lane >> 2, tig = lane & 3;
    const int qt = c_item[blockIdx.x][0];
    const int lo = c_item[blockIdx.x][1];
    const int hi = c_item[blockIdx.x][2];
    const int c0 = blockIdx.y * 128;
    const int b = blockIdx.z;
    const int qbase = b * 1024 + qt * 64;

    // S-phase warp grid: 2(m) x 4(n), warp tile 32x16
    const int mS = 32 * (wid >> 2), nS = 16 * (wid & 3);
    // O-phase warp grid: 2(m) x 4(n), warp tile 32x32
    const int mO = 32 * (wid & 1), nO = 32 * (wid >> 1);

    // load Q tile [64][132], tf32
    #pragma unroll
    for (int s = 0; s < 8; s++) {
        int slot = tid + s * 256;
        int r = slot >> 5;
        int f = (slot & 31) << 2;
        float4 v = *(const float4*)&Q2[(size_t)(qbase + r) * 128 + f];
        uint4 u;
        u.x = f2t(v.x); u.y = f2t(v.y); u.z = f2t(v.z); u.w = f2t(v.w);
        *(uint4*)&sQ[r * 132 + f] = u;
    }

    float acc[2][4][4];
    #pragma unroll
    for (int mf = 0; mf < 2; mf++)
        #pragma unroll
        for (int nf = 0; nf < 4; nf++)
            #pragma unroll
            for (int e = 0; e < 4; e++) acc[mf][nf][e] = 0.f;

    for (int kt = lo; kt < hi; kt++) {
        __syncthreads();
        const int kbase = b * 1024 + kt * 64;
        #pragma unroll
        for (int s = 0; s < 8; s++) {
            int slot = tid + s * 256;
            int r = slot >> 5;
            int f = (slot & 31) << 2;
            float4 v = *(const float4*)&K2[(size_t)(kbase + r) * 128 + f];
            uint4 u;
            u.x = f2t(v.x); u.y = f2t(v.y); u.z = f2t(v.z); u.w = f2t(v.w);
            *(uint4*)&sK[r * 132 + f] = u;
        }
        #pragma unroll
        for (int s = 0; s < 8; s++) {
            int slot = tid + s * 256;
            int r = slot >> 5;
            int f = (slot & 31) << 2;
            float4 v = *(const float4*)&Vb[(size_t)(kbase + r) * LDH + c0 + f];
            uint4 u;
            u.x = f2t(v.x); u.y = f2t(v.y); u.z = f2t(v.z); u.w = f2t(v.w);
            *(uint4*)&sV[r * 136 + f] = u;
        }
        __syncthreads();

        // S = Qtile @ Ktile^T (64x64)
        float sacc[2][2][4];
        #pragma unroll
        for (int mf = 0; mf < 2; mf++)
            #pragma unroll
            for (int nf = 0; nf < 2; nf++)
                #pragma unroll
                for (int e = 0; e < 4; e++) sacc[mf][nf][e] = 0.f;

        #pragma unroll
        for (int ks = 0; ks < 16; ks++) {
            int kb = ks * 8;
            uint32_t a[2][4], bb[2][2];
            #pragma unroll
            for (int mf = 0; mf < 2; mf++) {
                int r0 = mS + mf * 16 + group;
                a[mf][0] = sQ[r0 * 132 + kb + tig];
                a[mf][1] = sQ[(r0 + 8) * 132 + kb + tig];
                a[mf][2] = sQ[r0 * 132 + kb + tig + 4];
                a[mf][3] = sQ[(r0 + 8) * 132 + kb + tig + 4];
            }
            #pragma unroll
            for (int nf = 0; nf < 2; nf++) {
                int n0 = nS + nf * 8 + group;
                bb[nf][0] = sK[n0 * 132 + kb + tig];
                bb[nf][1] = sK[n0 * 132 + kb + tig + 4];
            }
            #pragma unroll
            for (int mf = 0; mf < 2; mf++)
                #pragma unroll
                for (int nf = 0; nf < 2; nf++)
                    mma8(sacc[mf][nf], a[mf], bb[nf]);
        }

        // causal mask (inclusive) on diagonal tile, then store S (tf32)
        #pragma unroll
        for (int mf = 0; mf < 2; mf++) {
            int row = mS + mf * 16 + group;
            #pragma unroll
            for (int nf = 0; nf < 2; nf++) {
                int col = nS + nf * 8 + 2 * tig;
                float s0 = sacc[mf][nf][0], s1 = sacc[mf][nf][1];
                float s2 = sacc[mf][nf][2], s3 = sacc[mf][nf][3];
                if (kt == qt) {
                    if (col > row) s0 = 0.f;
                    if (col + 1 > row) s1 = 0.f;
                    if (col > row + 8) s2 = 0.f;
                    if (col + 1 > row + 8) s3 = 0.f;
                }
                *(uint2*)&sS[row * 68 + col] = make_uint2(f2t(s0), f2t(s1));
                *(uint2*)&sS[(row + 8) * 68 + col] = make_uint2(f2t(s2), f2t(s3));
            }
        }
        __syncthreads();

        // O += S @ Vtile (64 x 128)
        #pragma unroll
        for (int ks = 0; ks < 8; ks++) {
            int kb = ks * 8;
            uint32_t a[2][4], bb[4][2];
            #pragma unroll
            for (int mf = 0; mf < 2; mf++) {
                int r0 = mO + mf * 16 + group;
                a[mf][0] = sS[r0 * 68 + kb + tig];
                a[mf][1] = sS[(r0 + 8) * 68 + kb + tig];
                a[mf][2] = sS[r0 * 68 + kb + tig + 4];
                a[mf][3] = sS[(r0 + 8) * 68 + kb + tig + 4];
            }
            #pragma unroll
            for (int nf = 0; nf < 4; nf++) {
                int n0 = nO + nf * 8 + group;
                bb[nf][0] = sV[(kb + tig) * 136 + n0];
                bb[nf][1] = sV[(kb + tig + 4) * 136 + n0];
            }
            #pragma unroll
            for (int mf = 0; mf < 2; mf++)
                #pragma unroll
                for (int nf = 0; nf < 4; nf++)
                    mma8(acc[mf][nf], a[mf], bb[nf]);
        }
    }

    float* dst = (lo == 0) ? ret : ret2;
    #pragma unroll
    for (int mf = 0; mf < 2; mf++) {
        int row = qbase + mO + mf * 16 + group;
        #pragma unroll
        for (int nf = 0; nf < 4; nf++) {
            int col = c0 + nO + nf * 8 + 2 * tig;
            *(float2*)&dst[(size_t)row * 256 + col] =
                make_float2(acc[mf][nf][0], acc[mf][nf][1]);
            *(float2*)&dst[(size_t)(row + 8) * 256 + col] =
                make_float2(acc[mf][nf][2], acc[mf][nf][3]);
        }
    }
}

// ---------------------------------------------------------------------------
// partial-sum + position scale + LayerNorm. one block/row, 256 threads.
// ---------------------------------------------------------------------------
__global__ void __launch_bounds__(256) ln_kernel(
    const float* __restrict__ ret, const float* __restrict__ ret2,
    const float* __restrict__ g, const float* __restrict__ bta,
    float* __restrict__ out)
{
    int row = blockIdx.x;
    int t = threadIdx.x;
    int l = row & 1023;
    float v = ret[(size_t)row * 256 + t];
    if (l >= 512) v += ret2[(size_t)row * 256 + t];
    v *= rsqrtf((float)(l + 1) * 64.0f);

    float s = v, s2 = v * v;
    #pragma unroll
    for (int o = 16; o > 0; o >>= 1) {
        s += __shfl_xor_sync(0xFFFFFFFFu, s, o);
        s2 += __shfl_xor_sync(0xFFFFFFFFu, s2, o);
    }
    __shared__ float ws[8], ws2[8];
    int w = t >> 5, ln = t & 31;
    if (ln == 0) { ws[w] = s; ws2[w] = s2; }
    __syncthreads();
    if (w == 0) {
        float a = (ln < 8) ? ws[ln] : 0.f;
        float a2 = (ln < 8) ? ws2[ln] : 0.f;
        #pragma unroll
        for (int o = 4; o > 0; o >>= 1) {
            a += __shfl_xor_sync(0xFFFFFFFFu, a, o);
            a2 += __shfl_xor_sync(0xFFFFFFFFu, a2, o);
        }
        if (ln == 0) { ws[0] = a; ws2[0] = a2; }
    }
    __syncthreads();
    float mean = ws[0] * (1.f / 256.f);
    float var = fmaxf(ws2[0] * (1.f / 256.f) - mean * mean, 0.f);
    out[(size_t)row * 256 + t] = (v - mean) * rsqrtf(var + 1e-5f) * g[t] + bta[t];
}

// ---------------------------------------------------------------------------
// out = x + rln @ out_w^T + out_b.  grid (32, 4).
// ---------------------------------------------------------------------------
__global__ void __launch_bounds__(256) gemm_out(
    const float* __restrict__ rln, const float* __restrict__ W,
    const float* __restrict__ Bs, const float* __restrict__ x,
    float* __restrict__ out)
{
    __shared__ uint32_t sA[128 * TA_LD];
    __shared__ uint32_t sB[64 * TA_LD];
    const int tid = threadIdx.x, lane = tid & 31, wid = tid >> 5;
    const int group = lane >> 2, tig = lane & 3;
    const int warpM = wid & 3, warpN = wid >> 2;
    const int m0 = blockIdx.x * 128;
    const int n0 = blockIdx.y * 64;

    float acc[2][4][4] = {};
    tile_mma<false>(rln + (size_t)m0 * 256, 256, W + (size_t)n0 * 256, 64,
                    sA, sB, acc, warpM, warpN, group, tig);

    #pragma unroll
    for (int mf = 0; mf < 2; mf++) {
        int r0 = m0 + warpM * 32 + mf * 16 + group;
        #pragma unroll
        for (int nf = 0; nf < 4; nf++) {
            int colL = warpN * 32 + nf * 8 + 2 * tig;
            int n = n0 + colL;
            float bv0 = Bs[n], bv1 = Bs[n + 1];
            float2 x0 = *(const float2*)&x[(size_t)r0 * 256 + n];
            float2 x1 = *(const float2*)&x[(size_t)(r0 + 8) * 256 + n];
            *(float2*)&out[(size_t)r0 * 256 + n] =
                make_float2(acc[mf][nf][0] + bv0 + x0.x, acc[mf][nf][1] + bv1 + x0.y);
            *(float2*)&out[(size_t)(r0 + 8) * 256 + n] =
                make_float2(acc[mf][nf][2] + bv0 + x1.x, acc[mf][nf][3] + bv1 + x1.y);
        }
    }
}

// ---------------------------------------------------------------------------
extern "C" void kernel_launch(void* const* d_in, const int* in_sizes, int n_in,
                              void* d_out, int out_size)
{
    (void)in_sizes; (void)n_in; (void)out_size;
    const float* x     = (const float*)d_in[0];
    const float* kp_w1 = (const float*)d_in[1];
    const float* kp_b1 = (const float*)d_in[2];
    const float* kp_w2 = (const float*)d_in[3];
    const float* kp_b2 = (const float*)d_in[4];
    const float* qp_w1 = (const float*)d_in[5];
    const float* qp_b1 = (const float*)d_in[6];
    const float* qp_w2 = (const float*)d_in[7];
    const float* qp_b2 = (const float*)d_in[8];
    const float* kh_w1 = (const float*)d_in[9];
    const float* kh_b1 = (const float*)d_in[10];
    const float* kh_w2 = (const float*)d_in[11];
    const float* kh_b2 = (const float*)d_in[12];
    const float* qh_w1 = (const float*)d_in[13];
    const float* qh_b1 = (const float*)d_in[14];
    const float* qh_w2 = (const float*)d_in[15];
    const float* qh_b2 = (const float*)d_in[16];
    const float* v_w   = (const float*)d_in[17];
    const float* v_b   = (const float*)d_in[18];
    const float* ln_g  = (const float*)d_in[19];
    const float* ln_b  = (const float*)d_in[20];
    const float* out_w = (const float*)d_in[21];
    const float* out_b = (const float*)d_in[22];
    float* out = (float*)d_out;

    float *hid, *k2, *q2, *ret, *ret2, *rln;
    cudaGetSymbolAddress((void**)&hid, g_hid);
    cudaGetSymbolAddress((void**)&k2, g_k2);
    cudaGetSymbolAddress((void**)&q2, g_q2);
    cudaGetSymbolAddress((void**)&ret, g_ret);
    cudaGetSymbolAddress((void**)&ret2, g_ret2);
    cudaGetSymbolAddress((void**)&rln, g_rln);

    dim3 blk(256);

    // 1. fused first layers + V projection (TF32 MMA)
    gemm_fused1<<<dim3(32, 20), blk>>>(x, kp_w1, kp_b1, qp_w1, qp_b1,
                                       kh_w1, kh_b1, qh_w1, qh_b1,
                                       v_w, v_b, hid);

    // 2. fused second layers -> phasor features (TF32 MMA)
    layer2_feat<<<dim3(32, 4), blk>>>(hid, kp_w2, kp_b2, qp_w2, qp_b2,
                                      kh_w2, kh_b2, qh_w2, qh_b2, k2, q2);

    // 3. balanced causal linear attention (TF32 MMA)
    static bool attr_set = false;
    if (!attr_set) {
        cudaFuncSetAttribute(attn_kernel, cudaFuncAttributeMaxDynamicSharedMemorySize,
                             ATTN_SMEM_BYTES);
        attr_set = true;
    }
    attn_kernel<<<dim3(24, 2, 4), blk, ATTN_SMEM_BYTES>>>(q2, k2, hid + 1024, ret, ret2);

    // 4. partial-sum + scale + LayerNorm
    ln_kernel<<<4096, blk>>>(ret, ret2, ln_g, ln_b, rln);

    // 5. output projection + residual (TF32 MMA)
    gemm_out<<<dim3(32, 4), blk>>>(rln, out_w, out_b, x, out);
}

// round 4
// speedup vs baseline: 4.0316x; 1.0391x over previous
#include <cuda_runtime.h>
#include <math.h>
#include <stdint.h>

// B=4, L=1024, D=256, N_PER=48, N_HYP=16, K=64, features 2K=128
#define M_ROWS 4096
#define LDH 1280
#define PI_F 3.14159265358979323846f
#define TA_LD 36   // smem k-chunk stride (36 mod 32 = 4 -> conflict-free frags)

// scratch
__device__ float g_hid[M_ROWS * LDH];   // [GELU(kp|qp|kh|qh hidden) | V]
__device__ float g_k2[M_ROWS * 128];
__device__ float g_q2[M_ROWS * 128];
__device__ float g_ret[M_ROWS * 256];
__device__ float g_ret2[M_ROWS * 256];

__device__ __forceinline__ float gelu_exact(float v) {
    return 0.5f * v * (1.0f + erff(v * 0.7071067811865475f));
}

__device__ __forceinline__ uint32_t f2t(float f) {
    uint32_t u;
    asm("cvt.rna.tf32.f32 %0, %1;" : "=r"(u) : "f"(f));
    return u;
}

__device__ __forceinline__ void mma8(float c[4], const uint32_t a[4], const uint32_t b[2]) {
    asm("mma.sync.aligned.m16n8k8.row.col.f32.tf32.tf32.f32 "
        "{%0,%1,%2,%3},{%4,%5,%6,%7},{%8,%9},{%0,%1,%2,%3};"
        : "+f"(c[0]), "+f"(c[1]), "+f"(c[2]), "+f"(c[3])
        : "r"(a[0]), "r"(a[1]), "r"(a[2]), "r"(a[3]), "r"(b[0]), "r"(b[1]));
}

// ===========================================================================
// pipelined 128x64 tile engine pieces
// sA buffer: 128*TA_LD u32 per stage, sB: 64*TA_LD per stage
// ===========================================================================
template <bool GUARD>
__device__ __forceinline__ void gl_load(
    const float* __restrict__ A, int lda,
    const float* __restrict__ W, int nvalid, int k0,
    float4 ra[4], float4 rw[2])
{
    const int tid = threadIdx.x;
    #pragma unroll
    for (int s = 0; s < 4; s++) {
        int slot = tid + s * 256;
        int r = slot >> 3;
        int kk = (slot & 7) << 2;
        ra[s] = *(const float4*)&A[(size_t)r * lda + k0 + kk];
    }
    #pragma unroll
    for (int s = 0; s < 2; s++) {
        int slot = tid + s * 256;
        int r = slot >> 3;
        int kk = (slot & 7) << 2;
        rw[s] = (GUARD && r >= nvalid) ? make_float4(0.f, 0.f, 0.f, 0.f)
                                       : *(const float4*)&W[(size_t)r * 256 + k0 + kk];
    }
}

__device__ __forceinline__ void gl_store(
    uint32_t* sA, uint32_t* sB, const float4 ra[4], const float4 rw[2])
{
    const int tid = threadIdx.x;
    #pragma unroll
    for (int s = 0; s < 4; s++) {
        int slot = tid + s * 256;
        int r = slot >> 3;
        int kk = (slot & 7) << 2;
        uint4 u;
        u.x = f2t(ra[s].x); u.y = f2t(ra[s].y); u.z = f2t(ra[s].z); u.w = f2t(ra[s].w);
        *(uint4*)&sA[r * TA_LD + kk] = u;
    }
    #pragma unroll
    for (int s = 0; s < 2; s++) {
        int slot = tid + s * 256;
        int r = slot >> 3;
        int kk = (slot & 7) << 2;
        uint4 u;
        u.x = f2t(rw[s].x); u.y = f2t(rw[s].y); u.z = f2t(rw[s].z); u.w = f2t(rw[s].w);
        *(uint4*)&sB[r * TA_LD + kk] = u;
    }
}

__device__ __forceinline__ void gl_compute(
    const uint32_t* sA, const uint32_t* sB, float acc[2][4][4],
    int warpM, int warpN, int group, int tig)
{
    #pragma unroll
    for (int ks = 0; ks < 4; ks++) {
        int kb = ks * 8;
        uint32_t a[2][4], b[4][2];
        #pragma unroll
        for (int mf = 0; mf < 2; mf++) {
            int r0 = warpM * 32 + mf * 16 + group;
            a[mf][0] = sA[r0 * TA_LD + kb + tig];
            a[mf][1] = sA[(r0 + 8) * TA_LD + kb + tig];
            a[mf][2] = sA[r0 * TA_LD + kb + tig + 4];
            a[mf][3] = sA[(r0 + 8) * TA_LD + kb + tig + 4];
        }
        #pragma unroll
        for (int nf = 0; nf < 4; nf++) {
            int n0 = warpN * 32 + nf * 8 + group;
            b[nf][0] = sB[n0 * TA_LD + kb + tig];
            b[nf][1] = sB[n0 * TA_LD + kb + tig + 4];
        }
        #pragma unroll
        for (int mf = 0; mf < 2; mf++)
            #pragma unroll
            for (int nf = 0; nf < 4; nf++)
                mma8(acc[mf][nf], a[mf], b[nf]);
    }
}

#define GEMM_SMEM_U32 (2 * 128 * TA_LD + 2 * 64 * TA_LD)   // 13824
#define GEMM_SMEM_BYTES (GEMM_SMEM_U32 * 4)

template <bool GUARD>
__device__ __forceinline__ void tile_mma_pipe(
    const float* __restrict__ A, int lda,
    const float* __restrict__ W, int nvalid,
    uint32_t* smu, float acc[2][4][4],
    int warpM, int warpN, int group, int tig)
{
    uint32_t* sA = smu;                       // 2 x 128*TA_LD
    uint32_t* sB = smu + 2 * 128 * TA_LD;     // 2 x 64*TA_LD
    float4 ra[4], rw[2];
    gl_load<GUARD>(A, lda, W, nvalid, 0, ra, rw);
    gl_store(sA, sB, ra, rw);
    __syncthreads();
    int p = 0;
    #pragma unroll
    for (int c = 0; c < 8; c++) {
        if (c < 7) gl_load<GUARD>(A, lda, W, nvalid, (c + 1) * 32, ra, rw);
        gl_compute(sA + p * 128 * TA_LD, sB + p * 64 * TA_LD, acc,
                   warpM, warpN, group, tig);
        if (c < 7) {
            gl_store(sA + (p ^ 1) * 128 * TA_LD, sB + (p ^ 1) * 64 * TA_LD, ra, rw);
            __syncthreads();
        }
        p ^= 1;
    }
}

// ---------------------------------------------------------------------------
// Fused first layers: hid[4096,1280] = [GELU(x@W1^T+b1) x4 | x@v_w^T+v_b]
// grid (32, 20)
// ---------------------------------------------------------------------------
__global__ void __launch_bounds__(256) gemm_fused1(
    const float* __restrict__ x,
    const float* __restrict__ w0, const float* __restrict__ b0,
    const float* __restrict__ w1, const float* __restrict__ b1,
    const float* __restrict__ w2, const float* __restrict__ b2,
    const float* __restrict__ w3, const float* __restrict__ b3,
    const float* __restrict__ w4, const float* __restrict__ b4,
    float* __restrict__ hid)
{
    extern __shared__ uint32_t smu[];
    const int tid = threadIdx.x, lane = tid & 31, wid = tid >> 5;
    const int group = lane >> 2, tig = lane & 3;
    const int warpM = wid & 3, warpN = wid >> 2;
    const int m0 = blockIdx.x * 128;
    const int by = blockIdx.y;
    const int seg = by >> 2;
    const int wrow = (by & 3) * 64;

    const float* W; const float* Bs;
    if      (seg == 0) { W = w0; Bs = b0; }
    else if (seg == 1) { W = w1; Bs = b1; }
    else if (seg == 2) { W = w2; Bs = b2; }
    else if (seg == 3) { W = w3; Bs = b3; }
    else               { W = w4; Bs = b4; }
    W += (size_t)wrow * 256;

    float acc[2][4][4] = {};
    tile_mma_pipe<false>(x + (size_t)m0 * 256, 256, W, 64, smu, acc,
                         warpM, warpN, group, tig);

    #pragma unroll
    for (int mf = 0; mf < 2; mf++) {
        int r0 = m0 + warpM * 32 + mf * 16 + group;
        #pragma unroll
        for (int nf = 0; nf < 4; nf++) {
            int colL = warpN * 32 + nf * 8 + 2 * tig;
            float bv0 = Bs[wrow + colL], bv1 = Bs[wrow + colL + 1];
            float v00 = acc[mf][nf][0] + bv0, v01 = acc[mf][nf][1] + bv1;
            float v10 = acc[mf][nf][2] + bv0, v11 = acc[mf][nf][3] + bv1;
            if (seg < 4) {
                v00 = gelu_exact(v00); v01 = gelu_exact(v01);
                v10 = gelu_exact(v10); v11 = gelu_exact(v11);
            }
            *(float2*)&hid[(size_t)r0 * LDH + by * 64 + colL] = make_float2(v00, v01);
            *(float2*)&hid[(size_t)(r0 + 8) * LDH + by * 64 + colL] = make_float2(v10, v11);
        }
    }
}

// ---------------------------------------------------------------------------
// Fused second layers + phasor features -> k2/q2 [4096,128].
// grid (32, 4): seg 0=kp->k2 per, 1=qp->q2 per, 2=kh->k2 hyp, 3=qh->q2 hyp
// feature layout: [per re 0..47 | hyp re 48..63 | per im 64..111 | hyp im 112..127]
// ---------------------------------------------------------------------------
__global__ void __launch_bounds__(256) layer2_feat(
    const float* __restrict__ hid,
    const float* __restrict__ w0, const float* __restrict__ b0,
    const float* __restrict__ w1, const float* __restrict__ b1,
    const float* __restrict__ w2, const float* __restrict__ b2,
    const float* __restrict__ w3, const float* __restrict__ b3,
    float* __restrict__ k2, float* __restrict__ q2)
{
    extern __shared__ uint32_t smu[];
    const int tid = threadIdx.x, lane = tid & 31, wid = tid >> 5;
    const int group = lane >> 2, tig = lane & 3;
    const int warpM = wid & 3, warpN = wid >> 2;
    const int m0 = blockIdx.x * 128;
    const int seg = blockIdx.y;

    const float* W; const float* Bs;
    if      (seg == 0) { W = w0; Bs = b0; }
    else if (seg == 1) { W = w1; Bs = b1; }
    else if (seg == 2) { W = w2; Bs = b2; }
    else               { W = w3; Bs = b3; }
    const int nseg = (seg < 2) ? 48 : 32;

    float acc[2][4][4] = {};
    tile_mma_pipe<true>(hid + (size_t)m0 * LDH + seg * 256, LDH, W, nseg, smu, acc,
                        warpM, warpN, group, tig);

    float* dst = (seg == 0 || seg == 2) ? k2 : q2;

    if (seg < 2) {
        #pragma unroll
        for (int mf = 0; mf < 2; mf++) {
            int r0 = m0 + warpM * 32 + mf * 16 + group;
            #pragma unroll
            for (int nf = 0; nf < 4; nf++) {
                int colL = warpN * 32 + nf * 8 + 2 * tig;
                #pragma unroll
                for (int e = 0; e < 4; e++) {
                    int n = colL + (e & 1);
                    int m = (e < 2) ? r0 : r0 + 8;
                    if (n < 48) {
                        float ang = tanhf(acc[mf][nf][e] + Bs[n]) * PI_F;
                        float s, c;
                        sincosf(ang, &s, &c);
                        dst[(size_t)m * 128 + n] = c;
                        dst[(size_t)m * 128 + 64 + n] = s;
                    }
                }
            }
        }
    } else {
        #pragma unroll
        for (int mf = 0; mf < 2; mf++) {
            int r0 = m0 + warpM * 32 + mf * 16 + group;
            #pragma unroll
            for (int nf = 0; nf < 4; nf++) {
                int colL = warpN * 32 + nf * 8 + 2 * tig;
                if (colL < 32) {
                    int jj = colL >> 1;
                    float B0 = Bs[colL], B1 = Bs[colL + 1];
                    #pragma unroll
                    for (int h = 0; h < 2; h++) {
                        int m = (h == 0) ? r0 : r0 + 8;
                        float x0 = tanhf(acc[mf][nf][2 * h + 0] + B0) * 0.9f;
                        float y0 = tanhf(acc[mf][nf][2 * h + 1] + B1) * 0.9f;
                        float r = sqrtf(x0 * x0 + y0 * y0);
                        float re, im;
                        if (r > 0.0f) {
                            float sc = (1.0f - r) / r;
                            re = x0 * sc; im = y0 * sc;
                        } else { re = 1.0f; im = 0.0f; }
                        dst[(size_t)m * 128 + 48 + jj] = re;
                        dst[(size_t)m * 128 + 112 + jj] = im;
                    }
                }
            }
        }
    }
}

// ---------------------------------------------------------------------------
// Balanced causal linear attention, TF32 MMA, pipelined KV loads.
// items: (qt, kv_lo, kv_hi); qt>=8 split. lo==0 -> ret else ret2.
// Position scale 1/sqrt((l+1)*64) applied in epilogue.
// grid (24 items, 2 d-splits, 4 batches), 256 threads.
// ---------------------------------------------------------------------------
__constant__ int c_item[24][3] = {
    {15, 0, 8}, {15, 8, 16}, {14, 7, 15}, {7, 0, 8},
    {14, 0, 7}, {13, 0, 7},  {13, 7, 14}, {12, 6, 13}, {6, 0, 7},
    {12, 0, 6}, {11, 0, 6},  {11, 6, 12}, {10, 5, 11}, {5, 0, 6},
    {10, 0, 5}, {9, 0, 5},   {9, 5, 10},  {8, 4, 9},   {4, 0, 5},
    {8, 0, 4},  {3, 0, 4},   {2, 0, 3},   {1, 0, 2},   {0, 0, 1}
};

// smem (u32): sQ[8448] sK[8448] sV0[8704] sV1[8704] sS[4352]
#define ATTN_SMEM_U32 (8448 + 8448 + 2 * 8704 + 4352)
#define ATTN_SMEM_BYTES (ATTN_SMEM_U32 * 4)

__global__ void __launch_bounds__(256) attn_kernel(
    const float* __restrict__ Q2, const float* __restrict__ K2,
    const float* __restrict__ Vb,   // hid + 1024, row stride LDH
    float* __restrict__ ret, float* __restrict__ ret2)
{
    extern __shared__ uint32_t smu[];
    uint32_t* sQ = smu;
    uint32_t* sK = smu + 8448;
    uint32_t* sV0 = smu + 16896;
    uint32_t* sV1 = smu + 25600;
    uint32_t* sS = smu + 34304;

    const int tid = threadIdx.x, lane = tid & 31, wid = tid >> 5;
    const int group = lane >> 2, tig = lane & 3;
    const int qt = c_item[blockIdx.x][0];
    const int lo = c_item[blockIdx.x][1];
    const int hi = c_item[blockIdx.x][2];
    const int c0 = blockIdx.y * 128;
    const int b = blockIdx.z;
    const int qbase = b * 1024 + qt * 64;

    const int mS = 32 * (wid >> 2), nS = 16 * (wid & 3);   // S-phase warp tile 32x16
    const int mO = 32 * (wid & 1), nO = 32 * (wid >> 1);   // O-phase warp tile 32x32

    // load Q tile [64][132], tf32
    #pragma unroll
    for (int s = 0; s < 8; s++) {
        int slot = tid + s * 256;
        int r = slot >> 5;
        int f = (slot & 31) << 2;
        float4 v = *(const float4*)&Q2[(size_t)(qbase + r) * 128 + f];
        uint4 u;
        u.x = f2t(v.x); u.y = f2t(v.y); u.z = f2t(v.z); u.w = f2t(v.w);
        *(uint4*)&sQ[r * 132 + f] = u;
    }

    // prologue: KV(lo) -> regs -> smem
    float4 rk[8], rv[8];
    {
        const int kbase = b * 1024 + lo * 64;
        #pragma unroll
        for (int s = 0; s < 8; s++) {
            int slot = tid + s * 256;
            int r = slot >> 5;
            int f = (slot & 31) << 2;
            rk[s] = *(const float4*)&K2[(size_t)(kbase + r) * 128 + f];
            rv[s] = *(const float4*)&Vb[(size_t)(kbase + r) * LDH + c0 + f];
        }
        #pragma unroll
        for (int s = 0; s < 8; s++) {
            int slot = tid + s * 256;
            int r = slot >> 5;
            int f = (slot & 31) << 2;
            uint4 uk, uv;
            uk.x = f2t(rk[s].x); uk.y = f2t(rk[s].y); uk.z = f2t(rk[s].z); uk.w = f2t(rk[s].w);
            uv.x = f2t(rv[s].x); uv.y = f2t(rv[s].y); uv.z = f2t(rv[s].z); uv.w = f2t(rv[s].w);
            *(uint4*)&sK[r * 132 + f] = uk;
            *(uint4*)&sV0[r * 136 + f] = uv;
        }
    }
    __syncthreads();

    float acc[2][4][4];
    #pragma unroll
    for (int mf = 0; mf < 2; mf++)
        #pragma unroll
        for (int nf = 0; nf < 4; nf++)
            #pragma unroll
            for (int e = 0; e < 4; e++) acc[mf][nf][e] = 0.f;

    int p = 0;
    for (int kt = lo; kt < hi; kt++) {
        const bool more = (kt + 1 < hi);
        if (more) {  // prefetch next KV tile into regs (latency hidden by S+O)
            const int kbase = b * 1024 + (kt + 1) * 64;
            #pragma unroll
            for (int s = 0; s < 8; s++) {
                int slot = tid + s * 256;
                int r = slot >> 5;
                int f = (slot & 31) << 2;
                rk[s] = *(const float4*)&K2[(size_t)(kbase + r) * 128 + f];
                rv[s] = *(const float4*)&Vb[(size_t)(kbase + r) * LDH + c0 + f];
            }
        }

        // S = Qtile @ Ktile^T (64x64)
        float sacc[2][2][4];
        #pragma unroll
        for (int mf = 0; mf < 2; mf++)
            #pragma unroll
            for (int nf = 0; nf < 2; nf++)
                #pragma unroll
                for (int e = 0; e < 4; e++) sacc[mf][nf][e] = 0.f;

        #pragma unroll
        for (int ks = 0; ks < 16; ks++) {
            int kb = ks * 8;
            uint32_t a[2][4], bb[2][2];
            #pragma unroll
            for (int mf = 0; mf < 2; mf++) {
                int r0 = mS + mf * 16 + group;
                a[mf][0] = sQ[r0 * 132 + kb + tig];
                a[mf][1] = sQ[(r0 + 8) * 132 + kb + tig];
                a[mf][2] = sQ[r0 * 132 + kb + tig + 4];
                a[mf][3] = sQ[(r0 + 8) * 132 + kb + tig + 4];
            }
            #pragma unroll
            for (int nf = 0; nf < 2; nf++) {
                int n0 = nS + nf * 8 + group;
                bb[nf][0] = sK[n0 * 132 + kb + tig];
                bb[nf][1] = sK[n0 * 132 + kb + tig + 4];
            }
            #pragma unroll
            for (int mf = 0; mf < 2; mf++)
                #pragma unroll
                for (int nf = 0; nf < 2; nf++)
                    mma8(sacc[mf][nf], a[mf], bb[nf]);
        }

        // mask diagonal tile (inclusive causal), store S (tf32)
        #pragma unroll
        for (int mf = 0; mf < 2; mf++) {
            int row = mS + mf * 16 + group;
            #pragma unroll
            for (int nf = 0; nf < 2; nf++) {
                int col = nS + nf * 8 + 2 * tig;
                float s0 = sacc[mf][nf][0], s1 = sacc[mf][nf][1];
                float s2 = sacc[mf][nf][2], s3 = sacc[mf][nf][3];
                if (kt == qt) {
                    if (col > row) s0 = 0.f;
                    if (col + 1 > row) s1 = 0.f;
                    if (col > row + 8) s2 = 0.f;
                    if (col + 1 > row + 8) s3 = 0.f;
                }
                *(uint2*)&sS[row * 68 + col] = make_uint2(f2t(s0), f2t(s1));
                *(uint2*)&sS[(row + 8) * 68 + col] = make_uint2(f2t(s2), f2t(s3));
            }
        }
        __syncthreads();   // sync_b: S visible; also all S-reads of sK done

        // O += S @ Vtile (64 x 128)
        const uint32_t* sVp = p ? sV1 : sV0;
        #pragma unroll
        for (int ks = 0; ks < 8; ks++) {
            int kb = ks * 8;
            uint32_t a[2][4], bb[4][2];
            #pragma unroll
            for (int mf = 0; mf < 2; mf++) {
                int r0 = mO + mf * 16 + group;
                a[mf][0] = sS[r0 * 68 + kb + tig];
                a[mf][1] = sS[(r0 + 8) * 68 + kb + tig];
                a[mf][2] = sS[r0 * 68 + kb + tig + 4];
                a[mf][3] = sS[(r0 + 8) * 68 + kb + tig + 4];
            }
            #pragma unroll
            for (int nf = 0; nf < 4; nf++) {
                int n0 = nO + nf * 8 + group;
                bb[nf][0] = sVp[(kb + tig) * 136 + n0];
                bb[nf][1] = sVp[(kb + tig + 4) * 136 + n0];
            }
            #pragma unroll
            for (int mf = 0; mf < 2; mf++)
                #pragma unroll
                for (int nf = 0; nf < 4; nf++)
                    mma8(acc[mf][nf], a[mf], bb[nf]);
        }

        if (more) {
            // store next KV: sK overwrite safe (sync_b passed), V to other buffer
            uint32_t* sVn = p ? sV0 : sV1;
            #pragma unroll
            for (int s = 0; s < 8; s++) {
                int slot = tid + s * 256;
                int r = slot >> 5;
                int f = (slot & 31) << 2;
                uint4 uk, uv;
                uk.x = f2t(rk[s].x); uk.y = f2t(rk[s].y); uk.z = f2t(rk[s].z); uk.w = f2t(rk[s].w);
                uv.x = f2t(rv[s].x); uv.y = f2t(rv[s].y); uv.z = f2t(rv[s].z); uv.w = f2t(rv[s].w);
                *(uint4*)&sK[r * 132 + f] = uk;
                *(uint4*)&sVn[r * 136 + f] = uv;
            }
            __syncthreads();   // sync_a: next tile ready
            p ^= 1;
        }
    }

    // epilogue with position scale
    float* dst = (lo == 0) ? ret : ret2;
    #pragma unroll
    for (int mf = 0; mf < 2; mf++) {
        int rl = mO + mf * 16 + group;
        int row = qbase + rl;
        float sc0 = rsqrtf((float)(qt * 64 + rl + 1) * 64.0f);
        float sc1 = rsqrtf((float)(qt * 64 + rl + 9) * 64.0f);
        #pragma unroll
        for (int nf = 0; nf < 4; nf++) {
            int col = c0 + nO + nf * 8 + 2 * tig;
            *(float2*)&dst[(size_t)row * 256 + col] =
                make_float2(acc[mf][nf][0] * sc0, acc[mf][nf][1] * sc0);
            *(float2*)&dst[(size_t)(row + 8) * 256 + col] =
                make_float2(acc[mf][nf][2] * sc1, acc[mf][nf][3] * sc1);
        }
    }
}

// ---------------------------------------------------------------------------
// Fused LayerNorm + output projection + residual:
// out = x + LN(ret(+ret2)) @ out_w^T + out_b.  grid (32, 4).
// smem layout (u32): [pipe 13824 | sG 256 | sBt 256 | sMean 128 | sRstd 128]
// ---------------------------------------------------------------------------
#define OUT_SMEM_U32 (GEMM_SMEM_U32 + 256 + 256 + 128 + 128)
#define OUT_SMEM_BYTES (OUT_SMEM_U32 * 4)

__global__ void __launch_bounds__(256) gemm_out_ln(
    const float* __restrict__ ret, const float* __restrict__ ret2,
    const float* __restrict__ g, const float* __restrict__ bta,
    const float* __restrict__ W, const float* __restrict__ Bs,
    const float* __restrict__ x, float* __restrict__ out)
{
    extern __shared__ uint32_t smu[];
    float* sG = (float*)(smu + GEMM_SMEM_U32);
    float* sBt = sG + 256;
    float* sMean = sBt + 256;
    float* sRstd = sMean + 128;
    float* ps = (float*)smu;         // alias pipe buffers during stats pass
    float* ps2 = ps + 256;

    const int tid = threadIdx.x, lane = tid & 31, wid = tid >> 5;
    const int group = lane >> 2, tig = lane & 3;
    const int warpM = wid & 3, warpN = wid >> 2;
    const int m0 = blockIdx.x * 128;
    const int n0 = blockIdx.y * 64;

    // gamma/beta to smem
    sG[tid] = g[tid];
    sBt[tid] = bta[tid];

    // --- pass 1: row stats (ret already position-scaled; add ret2 for l>=512)
    {
        int r = tid & 127, h = tid >> 7;            // half h covers 128 cols
        int row = m0 + r;
        bool add2 = (row & 1023) >= 512;
        const float* p0 = ret + (size_t)row * 256 + h * 128;
        const float* p1 = ret2 + (size_t)row * 256 + h * 128;
        float s = 0.f, s2 = 0.f;
        #pragma unroll 8
        for (int j = 0; j < 32; j++) {
            float4 v = *(const float4*)&p0[j * 4];
            if (add2) {
                float4 w2 = *(const float4*)&p1[j * 4];
                v.x += w2.x; v.y += w2.y; v.z += w2.z; v.w += w2.w;
            }
            s += v.x + v.y + v.z + v.w;
            s2 += v.x * v.x + v.y * v.y + v.z * v.z + v.w * v.w;
        }
        ps[tid] = s; ps2[tid] = s2;
        __syncthreads();
        if (tid < 128) {
            float st = ps[tid] + ps[tid + 128];
            float st2 = ps2[tid] + ps2[tid + 128];
            float mean = st * (1.f / 256.f);
            float var = fmaxf(st2 * (1.f / 256.f) - mean * mean, 0.f);
            sMean[tid] = mean;
            sRstd[tid] = rsqrtf(var + 1e-5f);
        }
        __syncthreads();
    }

    // --- pass 2: pipelined GEMM with on-the-fly LN of A
    uint32_t* sA = smu;
    uint32_t* sB = smu + 2 * 128 * TA_LD;
    const float* Wn = W + (size_t)n0 * 256;
    float acc[2][4][4] = {};
    float4 ra[4], rw[2];

    auto ln_load = [&](int k0) {
        #pragma unroll
        for (int s = 0; s < 4; s++) {
            int slot = tid + s * 256;
            int r = slot >> 3;
            int kk = (slot & 7) << 2;
            int row = m0 + r;
            float4 v = *(const float4*)&ret[(size_t)row * 256 + k0 + kk];
            if ((row & 1023) >= 512) {
                float4 v2 = *(const float4*)&ret2[(size_t)row * 256 + k0 + kk];
                v.x += v2.x; v.y += v2.y; v.z += v2.z; v.w += v2.w;
            }
            float mean = sMean[r], rs = sRstd[r];
            v.x = (v.x - mean) * rs * sG[k0 + kk + 0] + sBt[k0 + kk + 0];
            v.y = (v.y - mean) * rs * sG[k0 + kk + 1] + sBt[k0 + kk + 1];
            v.z = (v.z - mean) * rs * sG[k0 + kk + 2] + sBt[k0 + kk + 2];
            v.w = (v.w - mean) * rs * sG[k0 + kk + 3] + sBt[k0 + kk + 3];
            ra[s] = v;
        }
        #pragma unroll
        for (int s = 0; s < 2; s++) {
            int slot = tid + s * 256;
            int r = slot >> 3;
            int kk = (slot & 7) << 2;
            rw[s] = *(const float4*)&Wn[(size_t)r * 256 + k0 + kk];
        }
    };

    ln_load(0);
    gl_store(sA, sB, ra, rw);
    __syncthreads();
    int p = 0;
    #pragma unroll
    for (int c = 0; c < 8; c++) {
        if (c < 7) ln_load((c + 1) * 32);
        gl_compute(sA + p * 128 * TA_LD, sB + p * 64 * TA_LD, acc,
                   warpM, warpN, group, tig);
        if (c < 7) {
            gl_store(sA + (p ^ 1) * 128 * TA_LD, sB + (p ^ 1) * 64 * TA_LD, ra, rw);
            __syncthreads();
        }
        p ^= 1;
    }

    #pragma unroll
    for (int mf = 0; mf < 2; mf++) {
        int r0 = m0 + warpM * 32 + mf * 16 + group;
        #pragma unroll
        for (int nf = 0; nf < 4; nf++) {
            int colL = warpN * 32 + nf * 8 + 2 * tig;
            int n = n0 + colL;
            float bv0 = Bs[n], bv1 = Bs[n + 1];
            float2 x0 = *(const float2*)&x[(size_t)r0 * 256 + n];
            float2 x1 = *(const float2*)&x[(size_t)(r0 + 8) * 256 + n];
            *(float2*)&out[(size_t)r0 * 256 + n] =
                make_float2(acc[mf][nf][0] + bv0 + x0.x, acc[mf][nf][1] + bv1 + x0.y);
            *(float2*)&out[(size_t)(r0 + 8) * 256 + n] =
                make_float2(acc[mf][nf][2] + bv0 + x1.x, acc[mf][nf][3] + bv1 + x1.y);
        }
    }
}

// ---------------------------------------------------------------------------
extern "C" void kernel_launch(void* const* d_in, const int* in_sizes, int n_in,
                              void* d_out, int out_size)
{
    (void)in_sizes; (void)n_in; (void)out_size;
    const float* x     = (const float*)d_in[0];
    const float* kp_w1 = (const float*)d_in[1];
    const float* kp_b1 = (const float*)d_in[2];
    const float* kp_w2 = (const float*)d_in[3];
    const float* kp_b2 = (const float*)d_in[4];
    const float* qp_w1 = (const float*)d_in[5];
    const float* qp_b1 = (const float*)d_in[6];
    const float* qp_w2 = (const float*)d_in[7];
    const float* qp_b2 = (const float*)d_in[8];
    const float* kh_w1 = (const float*)d_in[9];
    const float* kh_b1 = (const float*)d_in[10];
    const float* kh_w2 = (const float*)d_in[11];
    const float* kh_b2 = (const float*)d_in[12];
    const float* qh_w1 = (const float*)d_in[13];
    const float* qh_b1 = (const float*)d_in[14];
    const float* qh_w2 = (const float*)d_in[15];
    const float* qh_b2 = (const float*)d_in[16];
    const float* v_w   = (const float*)d_in[17];
    const float* v_b   = (const float*)d_in[18];
    const float* ln_g  = (const float*)d_in[19];
    const float* ln_b  = (const float*)d_in[20];
    const float* out_w = (const float*)d_in[21];
    const float* out_b = (const float*)d_in[22];
    float* out = (float*)d_out;

    float *hid, *k2, *q2, *ret, *ret2;
    cudaGetSymbolAddress((void**)&hid, g_hid);
    cudaGetSymbolAddress((void**)&k2, g_k2);
    cudaGetSymbolAddress((void**)&q2, g_q2);
    cudaGetSymbolAddress((void**)&ret, g_ret);
    cudaGetSymbolAddress((void**)&ret2, g_ret2);

    static bool attr_set = false;
    if (!attr_set) {
        cudaFuncSetAttribute(gemm_fused1, cudaFuncAttributeMaxDynamicSharedMemorySize,
                             GEMM_SMEM_BYTES);
        cudaFuncSetAttribute(layer2_feat, cudaFuncAttributeMaxDynamicSharedMemorySize,
                             GEMM_SMEM_BYTES);
        cudaFuncSetAttribute(attn_kernel, cudaFuncAttributeMaxDynamicSharedMemorySize,
                             ATTN_SMEM_BYTES);
        cudaFuncSetAttribute(gemm_out_ln, cudaFuncAttributeMaxDynamicSharedMemorySize,
                             OUT_SMEM_BYTES);
        attr_set = true;
    }

    dim3 blk(256);

    // 1. fused first layers + V projection
    gemm_fused1<<<dim3(32, 20), blk, GEMM_SMEM_BYTES>>>(
        x, kp_w1, kp_b1, qp_w1, qp_b1, kh_w1, kh_b1, qh_w1, qh_b1, v_w, v_b, hid);

    // 2. fused second layers -> phasor features
    layer2_feat<<<dim3(32, 4), blk, GEMM_SMEM_BYTES>>>(
        hid, kp_w2, kp_b2, qp_w2, qp_b2, kh_w2, kh_b2, qh_w2, qh_b2, k2, q2);

    // 3. balanced causal linear attention (scale fused)
    attn_kernel<<<dim3(24, 2, 4), blk, ATTN_SMEM_BYTES>>>(q2, k2, hid + 1024, ret, ret2);

    // 4. fused LN + output projection + residual
    gemm_out_ln<<<dim3(32, 4), blk, OUT_SMEM_BYTES>>>(
        ret, ret2, ln_g, ln_b, out_w, out_b, x, out);
}

// round 5
// speedup vs baseline: 4.3197x; 1.0715x over previous
#include <cuda_runtime.h>
#include <math.h>
#include <stdint.h>

// B=4, L=1024, D=256, N_PER=48, N_HYP=16, K=64, features 2K=128
#define M_ROWS 4096
#define LDH 1280
#define PI_F 3.14159265358979323846f
#define TA_LD 36   // smem k-chunk stride (36 mod 32 = 4 -> conflict-free frags)

// scratch
__device__ float g_hid[M_ROWS * LDH];   // [GELU(kp|qp|kh|qh hidden) | V]
__device__ float g_k2[M_ROWS * 128];
__device__ float g_q2[M_ROWS * 128];
__device__ float g_ret[M_ROWS * 256];
__device__ float g_ret2[M_ROWS * 256];
__device__ float g_rln[M_ROWS * 256];

__device__ __forceinline__ float gelu_exact(float v) {
    return 0.5f * v * (1.0f + erff(v * 0.7071067811865475f));
}

// ---- cp.async helpers -----------------------------------------------------
__device__ __forceinline__ void cpa16(void* s, const void* g) {
    uint32_t sa = (uint32_t)__cvta_generic_to_shared(s);
    asm volatile("cp.async.cg.shared.global [%0], [%1], 16;" :: "r"(sa), "l"(g));
}
__device__ __forceinline__ void cpa16z(void* s, const void* g, int sz) {
    uint32_t sa = (uint32_t)__cvta_generic_to_shared(s);
    asm volatile("cp.async.cg.shared.global [%0], [%1], 16, %2;" :: "r"(sa), "l"(g), "r"(sz));
}
#define CP_COMMIT() asm volatile("cp.async.commit_group;" ::: "memory")
#define CP_WAIT(N)  asm volatile("cp.async.wait_group %0;" :: "n"(N) : "memory")

// raw fp32 bits fed to mma.tf32 (HW truncates to tf32)
__device__ __forceinline__ void mma8(float c[4], const uint32_t a[4], const uint32_t b[2]) {
    asm("mma.sync.aligned.m16n8k8.row.col.f32.tf32.tf32.f32 "
        "{%0,%1,%2,%3},{%4,%5,%6,%7},{%8,%9},{%0,%1,%2,%3};"
        : "+f"(c[0]), "+f"(c[1]), "+f"(c[2]), "+f"(c[3])
        : "r"(a[0]), "r"(a[1]), "r"(a[2]), "r"(a[3]), "r"(b[0]), "r"(b[1]));
}

// ===========================================================================
// 128x64 tile engine (cp.async pipelined, 2-stage)
// ===========================================================================
template <bool GUARD>
__device__ __forceinline__ void issue_chunk128(
    const float* __restrict__ A, int lda,
    const float* __restrict__ W, int nvalid, int k0,
    float* sA, float* sB)
{
    const int tid = threadIdx.x;
    #pragma unroll
    for (int s = 0; s < 4; s++) {                 // A: 128 x 32
        int slot = tid + s * 256;
        int r = slot >> 3;
        int kk = (slot & 7) << 2;
        cpa16(&sA[r * TA_LD + kk], &A[(size_t)r * lda + k0 + kk]);
    }
    #pragma unroll
    for (int s = 0; s < 2; s++) {                 // W: 64 x 32
        int slot = tid + s * 256;
        int r = slot >> 3;
        int kk = (slot & 7) << 2;
        if (GUARD) {
            int rr = (r < nvalid) ? r : 0;
            cpa16z(&sB[r * TA_LD + kk], &W[(size_t)rr * 256 + k0 + kk],
                   (r < nvalid) ? 16 : 0);
        } else {
            cpa16(&sB[r * TA_LD + kk], &W[(size_t)r * 256 + k0 + kk]);
        }
    }
}

__device__ __forceinline__ void gl_compute(
    const uint32_t* sA, const uint32_t* sB, float acc[2][4][4],
    int warpM, int warpN, int group, int tig)
{
    #pragma unroll
    for (int ks = 0; ks < 4; ks++) {
        int kb = ks * 8;
        uint32_t a[2][4], b[4][2];
        #pragma unroll
        for (int mf = 0; mf < 2; mf++) {
            int r0 = warpM * 32 + mf * 16 + group;
            a[mf][0] = sA[r0 * TA_LD + kb + tig];
            a[mf][1] = sA[(r0 + 8) * TA_LD + kb + tig];
            a[mf][2] = sA[r0 * TA_LD + kb + tig + 4];
            a[mf][3] = sA[(r0 + 8) * TA_LD + kb + tig + 4];
        }
        #pragma unroll
        for (int nf = 0; nf < 4; nf++) {
            int n0 = warpN * 32 + nf * 8 + group;
            b[nf][0] = sB[n0 * TA_LD + kb + tig];
            b[nf][1] = sB[n0 * TA_LD + kb + tig + 4];
        }
        #pragma unroll
        for (int mf = 0; mf < 2; mf++)
            #pragma unroll
            for (int nf = 0; nf < 4; nf++)
                mma8(acc[mf][nf], a[mf], b[nf]);
    }
}

#define GEMM_SMEM_U32 (2 * 128 * TA_LD + 2 * 64 * TA_LD)   // 13824
#define GEMM_SMEM_BYTES (GEMM_SMEM_U32 * 4)

template <bool GUARD>
__device__ __forceinline__ void tile_mma_pipe(
    const float* __restrict__ A, int lda,
    const float* __restrict__ W, int nvalid,
    float* smf, float acc[2][4][4],
    int warpM, int warpN, int group, int tig)
{
    float* sA = smf;                       // 2 x 128*TA_LD
    float* sB = smf + 2 * 128 * TA_LD;     // 2 x 64*TA_LD
    issue_chunk128<GUARD>(A, lda, W, nvalid, 0, sA, sB);
    CP_COMMIT();
    int p = 0;
    #pragma unroll
    for (int c = 0; c < 8; c++) {
        if (c < 7) {
            issue_chunk128<GUARD>(A, lda, W, nvalid, (c + 1) * 32,
                                  sA + (p ^ 1) * 128 * TA_LD,
                                  sB + (p ^ 1) * 64 * TA_LD);
            CP_COMMIT();
            CP_WAIT(1);
        } else {
            CP_WAIT(0);
        }
        __syncthreads();
        gl_compute((const uint32_t*)(sA + p * 128 * TA_LD),
                   (const uint32_t*)(sB + p * 64 * TA_LD), acc,
                   warpM, warpN, group, tig);
        __syncthreads();
        p ^= 1;
    }
}

// ---------------------------------------------------------------------------
// Fused first layers: hid[4096,1280] = [GELU(x@W1^T+b1) x4 | x@v_w^T+v_b]
// grid (32, 20)
// ---------------------------------------------------------------------------
__global__ void __launch_bounds__(256) gemm_fused1(
    const float* __restrict__ x,
    const float* __restrict__ w0, const float* __restrict__ b0,
    const float* __restrict__ w1, const float* __restrict__ b1,
    const float* __restrict__ w2, const float* __restrict__ b2,
    const float* __restrict__ w3, const float* __restrict__ b3,
    const float* __restrict__ w4, const float* __restrict__ b4,
    float* __restrict__ hid)
{
    extern __shared__ float smf[];
    const int tid = threadIdx.x, lane = tid & 31, wid = tid >> 5;
    const int group = lane >> 2, tig = lane & 3;
    const int warpM = wid & 3, warpN = wid >> 2;
    const int m0 = blockIdx.x * 128;
    const int by = blockIdx.y;
    const int seg = by >> 2;
    const int wrow = (by & 3) * 64;

    const float* W; const float* Bs;
    if      (seg == 0) { W = w0; Bs = b0; }
    else if (seg == 1) { W = w1; Bs = b1; }
    else if (seg == 2) { W = w2; Bs = b2; }
    else if (seg == 3) { W = w3; Bs = b3; }
    else               { W = w4; Bs = b4; }
    W += (size_t)wrow * 256;

    float acc[2][4][4] = {};
    tile_mma_pipe<false>(x + (size_t)m0 * 256, 256, W, 64, smf, acc,
                         warpM, warpN, group, tig);

    #pragma unroll
    for (int mf = 0; mf < 2; mf++) {
        int r0 = m0 + warpM * 32 + mf * 16 + group;
        #pragma unroll
        for (int nf = 0; nf < 4; nf++) {
            int colL = warpN * 32 + nf * 8 + 2 * tig;
            float bv0 = Bs[wrow + colL], bv1 = Bs[wrow + colL + 1];
            float v00 = acc[mf][nf][0] + bv0, v01 = acc[mf][nf][1] + bv1;
            float v10 = acc[mf][nf][2] + bv0, v11 = acc[mf][nf][3] + bv1;
            if (seg < 4) {
                v00 = gelu_exact(v00); v01 = gelu_exact(v01);
                v10 = gelu_exact(v10); v11 = gelu_exact(v11);
            }
            *(float2*)&hid[(size_t)r0 * LDH + by * 64 + colL] = make_float2(v00, v01);
            *(float2*)&hid[(size_t)(r0 + 8) * LDH + by * 64 + colL] = make_float2(v10, v11);
        }
    }
}

// ---------------------------------------------------------------------------
// Fused second layers + phasor features -> k2/q2 [4096,128].
// grid (32, 4): seg 0=kp->k2 per, 1=qp->q2 per, 2=kh->k2 hyp, 3=qh->q2 hyp
// feature layout: [per re 0..47 | hyp re 48..63 | per im 64..111 | hyp im 112..127]
// ---------------------------------------------------------------------------
__global__ void __launch_bounds__(256) layer2_feat(
    const float* __restrict__ hid,
    const float* __restrict__ w0, const float* __restrict__ b0,
    const float* __restrict__ w1, const float* __restrict__ b1,
    const float* __restrict__ w2, const float* __restrict__ b2,
    const float* __restrict__ w3, const float* __restrict__ b3,
    float* __restrict__ k2, float* __restrict__ q2)
{
    extern __shared__ float smf[];
    const int tid = threadIdx.x, lane = tid & 31, wid = tid >> 5;
    const int group = lane >> 2, tig = lane & 3;
    const int warpM = wid & 3, warpN = wid >> 2;
    const int m0 = blockIdx.x * 128;
    const int seg = blockIdx.y;

    const float* W; const float* Bs;
    if      (seg == 0) { W = w0; Bs = b0; }
    else if (seg == 1) { W = w1; Bs = b1; }
    else if (seg == 2) { W = w2; Bs = b2; }
    else               { W = w3; Bs = b3; }
    const int nseg = (seg < 2) ? 48 : 32;

    float acc[2][4][4] = {};
    tile_mma_pipe<true>(hid + (size_t)m0 * LDH + seg * 256, LDH, W, nseg, smf, acc,
                        warpM, warpN, group, tig);

    float* dst = (seg == 0 || seg == 2) ? k2 : q2;

    if (seg < 2) {
        #pragma unroll
        for (int mf = 0; mf < 2; mf++) {
            int r0 = m0 + warpM * 32 + mf * 16 + group;
            #pragma unroll
            for (int nf = 0; nf < 4; nf++) {
                int colL = warpN * 32 + nf * 8 + 2 * tig;
                #pragma unroll
                for (int e = 0; e < 4; e++) {
                    int n = colL + (e & 1);
                    int m = (e < 2) ? r0 : r0 + 8;
                    if (n < 48) {
                        float ang = tanhf(acc[mf][nf][e] + Bs[n]) * PI_F;
                        float s, c;
                        sincosf(ang, &s, &c);
                        dst[(size_t)m * 128 + n] = c;
                        dst[(size_t)m * 128 + 64 + n] = s;
                    }
                }
            }
        }
    } else {
        #pragma unroll
        for (int mf = 0; mf < 2; mf++) {
            int r0 = m0 + warpM * 32 + mf * 16 + group;
            #pragma unroll
            for (int nf = 0; nf < 4; nf++) {
                int colL = warpN * 32 + nf * 8 + 2 * tig;
                if (colL < 32) {
                    int jj = colL >> 1;
                    float B0 = Bs[colL], B1 = Bs[colL + 1];
                    #pragma unroll
                    for (int h = 0; h < 2; h++) {
                        int m = (h == 0) ? r0 : r0 + 8;
                        float x0 = tanhf(acc[mf][nf][2 * h + 0] + B0) * 0.9f;
                        float y0 = tanhf(acc[mf][nf][2 * h + 1] + B1) * 0.9f;
                        float r = sqrtf(x0 * x0 + y0 * y0);
                        float re, im;
                        if (r > 0.0f) {
                            float sc = (1.0f - r) / r;
                            re = x0 * sc; im = y0 * sc;
                        } else { re = 1.0f; im = 0.0f; }
                        dst[(size_t)m * 128 + 48 + jj] = re;
                        dst[(size_t)m * 128 + 112 + jj] = im;
                    }
                }
            }
        }
    }
}

// ---------------------------------------------------------------------------
// Balanced causal linear attention, cp.async double-buffered K/V.
// items: (qt, kv_lo, kv_hi); qt>=8 split. lo==0 -> ret else ret2.
// Position scale 1/sqrt((l+1)*64) applied in epilogue.
// grid (24 items, 2 d-splits, 4 batches), 256 threads.
// ---------------------------------------------------------------------------
__constant__ int c_item[24][3] = {
    {15, 0, 8}, {15, 8, 16}, {14, 7, 15}, {7, 0, 8},
    {14, 0, 7}, {13, 0, 7},  {13, 7, 14}, {12, 6, 13}, {6, 0, 7},
    {12, 0, 6}, {11, 0, 6},  {11, 6, 12}, {10, 5, 11}, {5, 0, 6},
    {10, 0, 5}, {9, 0, 5},   {9, 5, 10},  {8, 4, 9},   {4, 0, 5},
    {8, 0, 4},  {3, 0, 4},   {2, 0, 3},   {1, 0, 2},   {0, 0, 1}
};

// floats: sQ[8448] sK0[8448] sK1[8448] sV0[8704] sV1[8704] sS[4352]
#define ATTN_SMEM_U32 (8448 * 3 + 8704 * 2 + 4352)     // 47104
#define ATTN_SMEM_BYTES (ATTN_SMEM_U32 * 4)

__global__ void __launch_bounds__(256) attn_kernel(
    const float* __restrict__ Q2, const float* __restrict__ K2,
    const float* __restrict__ Vb,   // hid + 1024, row stride LDH
    float* __restrict__ ret, float* __restrict__ ret2)
{
    extern __shared__ float smf[];
    float* sQ = smf;
    float* sK[2] = { smf + 8448, smf + 16896 };
    float* sV[2] = { smf + 25344, smf + 34048 };
    float* sS = smf + 42752;

    const int tid = threadIdx.x, lane = tid & 31, wid = tid >> 5;
    const int group = lane >> 2, tig = lane & 3;
    const int qt = c_item[blockIdx.x][0];
    const int lo = c_item[blockIdx.x][1];
    const int hi = c_item[blockIdx.x][2];
    const int c0 = blockIdx.y * 128;
    const int b = blockIdx.z;
    const int qbase = b * 1024 + qt * 64;

    const int mS = 32 * (wid >> 2), nS = 16 * (wid & 3);   // S-phase warp tile 32x16
    const int mO = 32 * (wid & 1), nO = 32 * (wid >> 1);   // O-phase warp tile 32x32

    auto issue_kv = [&](int kt, int st) {
        const int kbase = b * 1024 + kt * 64;
        #pragma unroll
        for (int s = 0; s < 8; s++) {
            int slot = tid + s * 256;
            int r = slot >> 5;
            int f = (slot & 31) << 2;
            cpa16(&sK[st][r * 132 + f], &K2[(size_t)(kbase + r) * 128 + f]);
            cpa16(&sV[st][r * 136 + f], &Vb[(size_t)(kbase + r) * LDH + c0 + f]);
        }
    };

    // prologue: Q + KV(lo)
    #pragma unroll
    for (int s = 0; s < 8; s++) {
        int slot = tid + s * 256;
        int r = slot >> 5;
        int f = (slot & 31) << 2;
        cpa16(&sQ[r * 132 + f], &Q2[(size_t)(qbase + r) * 128 + f]);
    }
    issue_kv(lo, 0);
    CP_COMMIT();
    CP_WAIT(0);
    __syncthreads();

    float acc[2][4][4];
    #pragma unroll
    for (int mf = 0; mf < 2; mf++)
        #pragma unroll
        for (int nf = 0; nf < 4; nf++)
            #pragma unroll
            for (int e = 0; e < 4; e++) acc[mf][nf][e] = 0.f;

    int p = 0;
    for (int kt = lo; kt < hi; kt++) {
        const bool more = (kt + 1 < hi);
        if (more) {        // stage p^1 free (its readers finished last iter)
            issue_kv(kt + 1, p ^ 1);
            CP_COMMIT();
        }

        // S = Qtile @ Ktile^T (64x64)
        const uint32_t* sKu = (const uint32_t*)sK[p];
        const uint32_t* sQu = (const uint32_t*)sQ;
        float sacc[2][2][4];
        #pragma unroll
        for (int mf = 0; mf < 2; mf++)
            #pragma unroll
            for (int nf = 0; nf < 2; nf++)
                #pragma unroll
                for (int e = 0; e < 4; e++) sacc[mf][nf][e] = 0.f;

        #pragma unroll
        for (int ks = 0; ks < 16; ks++) {
            int kb = ks * 8;
            uint32_t a[2][4], bb[2][2];
            #pragma unroll
            for (int mf = 0; mf < 2; mf++) {
                int r0 = mS + mf * 16 + group;
                a[mf][0] = sQu[r0 * 132 + kb + tig];
                a[mf][1] = sQu[(r0 + 8) * 132 + kb + tig];
                a[mf][2] = sQu[r0 * 132 + kb + tig + 4];
                a[mf][3] = sQu[(r0 + 8) * 132 + kb + tig + 4];
            }
            #pragma unroll
            for (int nf = 0; nf < 2; nf++) {
                int n0 = nS + nf * 8 + group;
                bb[nf][0] = sKu[n0 * 132 + kb + tig];
                bb[nf][1] = sKu[n0 * 132 + kb + tig + 4];
            }
            #pragma unroll
            for (int mf = 0; mf < 2; mf++)
                #pragma unroll
                for (int nf = 0; nf < 2; nf++)
                    mma8(sacc[mf][nf], a[mf], bb[nf]);
        }

        // mask diagonal tile (inclusive causal), store S raw bits
        #pragma unroll
        for (int mf = 0; mf < 2; mf++) {
            int row = mS + mf * 16 + group;
            #pragma unroll
            for (int nf = 0; nf < 2; nf++) {
                int col = nS + nf * 8 + 2 * tig;
                float s0 = sacc[mf][nf][0], s1 = sacc[mf][nf][1];
                float s2 = sacc[mf][nf][2], s3 = sacc[mf][nf][3];
                if (kt == qt) {
                    if (col > row) s0 = 0.f;
                    if (col + 1 > row) s1 = 0.f;
                    if (col > row + 8) s2 = 0.f;
                    if (col + 1 > row + 8) s3 = 0.f;
                }
                *(float2*)&sS[row * 68 + col] = make_float2(s0, s1);
                *(float2*)&sS[(row + 8) * 68 + col] = make_float2(s2, s3);
            }
        }
        __syncthreads();   // sync1: S visible; K[p] reads done

        // O += S @ Vtile (64 x 128)
        const uint32_t* sVu = (const uint32_t*)sV[p];
        const uint32_t* sSu = (const uint32_t*)sS;
        #pragma unroll
        for (int ks = 0; ks < 8; ks++) {
            int kb = ks * 8;
            uint32_t a[2][4], bb[4][2];
            #pragma unroll
            for (int mf = 0; mf < 2; mf++) {
                int r0 = mO + mf * 16 + group;
                a[mf][0] = sSu[r0 * 68 + kb + tig];
                a[mf][1] = sSu[(r0 + 8) * 68 + kb + tig];
                a[mf][2] = sSu[r0 * 68 + kb + tig + 4];
                a[mf][3] = sSu[(r0 + 8) * 68 + kb + tig + 4];
            }
            #pragma unroll
            for (int nf = 0; nf < 4; nf++) {
                int n0 = nO + nf * 8 + group;
                bb[nf][0] = sVu[(kb + tig) * 136 + n0];
                bb[nf][1] = sVu[(kb + tig + 4) * 136 + n0];
            }
            #pragma unroll
            for (int mf = 0; mf < 2; mf++)
                #pragma unroll
                for (int nf = 0; nf < 4; nf++)
                    mma8(acc[mf][nf], a[mf], bb[nf]);
        }

        if (more) CP_WAIT(0);
        __syncthreads();   // sync2: next stage visible; S/V[p] reads done
        p ^= 1;
    }

    // epilogue with position scale
    float* dst = (lo == 0) ? ret : ret2;
    #pragma unroll
    for (int mf = 0; mf < 2; mf++) {
        int rl = mO + mf * 16 + group;
        int row = qbase + rl;
        float sc0 = rsqrtf((float)(qt * 64 + rl + 1) * 64.0f);
        float sc1 = rsqrtf((float)(qt * 64 + rl + 9) * 64.0f);
        #pragma unroll
        for (int nf = 0; nf < 4; nf++) {
            int col = c0 + nO + nf * 8 + 2 * tig;
            *(float2*)&dst[(size_t)row * 256 + col] =
                make_float2(acc[mf][nf][0] * sc0, acc[mf][nf][1] * sc0);
            *(float2*)&dst[(size_t)(row + 8) * 256 + col] =
                make_float2(acc[mf][nf][2] * sc1, acc[mf][nf][3] * sc1);
        }
    }
}

// ---------------------------------------------------------------------------
// Fast LayerNorm: warp per row, float4 loads. grid 512 x 256 thr.
// (ret already position-scaled; add ret2 for l>=512)
// ---------------------------------------------------------------------------
__global__ void __launch_bounds__(256) ln_kernel(
    const float* __restrict__ ret, const float* __restrict__ ret2,
    const float* __restrict__ g, const float* __restrict__ bta,
    float* __restrict__ rln)
{
    const int wid = threadIdx.x >> 5, lane = threadIdx.x & 31;
    const int row = blockIdx.x * 8 + wid;
    const int l = row & 1023;
    const float* p0 = ret + (size_t)row * 256;
    float4 a = *(const float4*)&p0[lane * 8];
    float4 c = *(const float4*)&p0[lane * 8 + 4];
    if (l >= 512) {
        const float* p1 = ret2 + (size_t)row * 256;
        float4 e = *(const float4*)&p1[lane * 8];
        float4 f = *(const float4*)&p1[lane * 8 + 4];
        a.x += e.x; a.y += e.y; a.z += e.z; a.w += e.w;
        c.x += f.x; c.y += f.y; c.z += f.z; c.w += f.w;
    }
    float s = a.x + a.y + a.z + a.w + c.x + c.y + c.z + c.w;
    float s2 = a.x * a.x + a.y * a.y + a.z * a.z + a.w * a.w
             + c.x * c.x + c.y * c.y + c.z * c.z + c.w * c.w;
    #pragma unroll
    for (int o = 16; o > 0; o >>= 1) {
        s += __shfl_xor_sync(0xFFFFFFFFu, s, o);
        s2 += __shfl_xor_sync(0xFFFFFFFFu, s2, o);
    }
    float mean = s * (1.f / 256.f);
    float var = fmaxf(s2 * (1.f / 256.f) - mean * mean, 0.f);
    float rs = rsqrtf(var + 1e-5f);

    float4 g0 = *(const float4*)&g[lane * 8];
    float4 g1 = *(const float4*)&g[lane * 8 + 4];
    float4 b0 = *(const float4*)&bta[lane * 8];
    float4 b1 = *(const float4*)&bta[lane * 8 + 4];
    float4 o0, o1;
    o0.x = (a.x - mean) * rs * g0.x + b0.x;
    o0.y = (a.y - mean) * rs * g0.y + b0.y;
    o0.z = (a.z - mean) * rs * g0.z + b0.z;
    o0.w = (a.w - mean) * rs * g0.w + b0.w;
    o1.x = (c.x - mean) * rs * g1.x + b1.x;
    o1.y = (c.y - mean) * rs * g1.y + b1.y;
    o1.z = (c.z - mean) * rs * g1.z + b1.z;
    o1.w = (c.w - mean) * rs * g1.w + b1.w;
    float* po = rln + (size_t)row * 256;
    *(float4*)&po[lane * 8] = o0;
    *(float4*)&po[lane * 8 + 4] = o1;
}

// ---------------------------------------------------------------------------
// out = x + rln @ out_w^T + out_b.  64x64 tiles, grid (64, 4), cp.async.
// warps: 2(m) x 4(n), warp tile 32x16.
// ---------------------------------------------------------------------------
#define OUT_SMEM_U32 (2 * 64 * TA_LD + 2 * 64 * TA_LD)   // 9216
#define OUT_SMEM_BYTES (OUT_SMEM_U32 * 4)

__global__ void __launch_bounds__(256) gemm_out(
    const float* __restrict__ rln, const float* __restrict__ W,
    const float* __restrict__ Bs, const float* __restrict__ x,
    float* __restrict__ out)
{
    extern __shared__ float smf[];
    float* sA = smf;                      // 2 x 64*TA_LD
    float* sB = smf + 2 * 64 * TA_LD;
    const int tid = threadIdx.x, lane = tid & 31, wid = tid >> 5;
    const int group = lane >> 2, tig = lane & 3;
    const int warpM = wid & 1, warpN = wid >> 1;
    const int m0 = blockIdx.x * 64;
    const int n0 = blockIdx.y * 64;
    const float* An = rln + (size_t)m0 * 256;
    const float* Wn = W + (size_t)n0 * 256;

    auto issue = [&](int k0, int st) {
        #pragma unroll
        for (int s = 0; s < 2; s++) {
            int slot = tid + s * 256;
            int r = slot >> 3;
            int kk = (slot & 7) << 2;
            cpa16(&sA[st * 64 * TA_LD + r * TA_LD + kk], &An[(size_t)r * 256 + k0 + kk]);
            cpa16(&sB[st * 64 * TA_LD + r * TA_LD + kk], &Wn[(size_t)r * 256 + k0 + kk]);
        }
    };

    float acc[2][2][4] = {};
    issue(0, 0);
    CP_COMMIT();
    int p = 0;
    #pragma unroll
    for (int c = 0; c < 8; c++) {
        if (c < 7) { issue((c + 1) * 32, p ^ 1); CP_COMMIT(); CP_WAIT(1); }
        else       { CP_WAIT(0); }
        __syncthreads();
        const uint32_t* uA = (const uint32_t*)(sA + p * 64 * TA_LD);
        const uint32_t* uB = (const uint32_t*)(sB + p * 64 * TA_LD);
        #pragma unroll
        for (int ks = 0; ks < 4; ks++) {
            int kb = ks * 8;
            uint32_t a[2][4], b[2][2];
            #pragma unroll
            for (int mf = 0; mf < 2; mf++) {
                int r0 = warpM * 32 + mf * 16 + group;
                a[mf][0] = uA[r0 * TA_LD + kb + tig];
                a[mf][1] = uA[(r0 + 8) * TA_LD + kb + tig];
                a[mf][2] = uA[r0 * TA_LD + kb + tig + 4];
                a[mf][3] = uA[(r0 + 8) * TA_LD + kb + tig + 4];
            }
            #pragma unroll
            for (int nf = 0; nf < 2; nf++) {
                int nn = warpN * 16 + nf * 8 + group;
                b[nf][0] = uB[nn * TA_LD + kb + tig];
                b[nf][1] = uB[nn * TA_LD + kb + tig + 4];
            }
            #pragma unroll
            for (int mf = 0; mf < 2; mf++)
                #pragma unroll
                for (int nf = 0; nf < 2; nf++)
                    mma8(acc[mf][nf], a[mf], b[nf]);
        }
        __syncthreads();
        p ^= 1;
    }

    #pragma unroll
    for (int mf = 0; mf < 2; mf++) {
        int r0 = m0 + warpM * 32 + mf * 16 + group;
        #pragma unroll
        for (int nf = 0; nf < 2; nf++) {
            int n = n0 + warpN * 16 + nf * 8 + 2 * tig;
            float bv0 = Bs[n], bv1 = Bs[n + 1];
            float2 x0 = *(const float2*)&x[(size_t)r0 * 256 + n];
            float2 x1 = *(const float2*)&x[(size_t)(r0 + 8) * 256 + n];
            *(float2*)&out[(size_t)r0 * 256 + n] =
                make_float2(acc[mf][nf][0] + bv0 + x0.x, acc[mf][nf][1] + bv1 + x0.y);
            *(float2*)&out[(size_t)(r0 + 8) * 256 + n] =
                make_float2(acc[mf][nf][2] + bv0 + x1.x, acc[mf][nf][3] + bv1 + x1.y);
        }
    }
}

// ---------------------------------------------------------------------------
extern "C" void kernel_launch(void* const* d_in, const int* in_sizes, int n_in,
                              void* d_out, int out_size)
{
    (void)in_sizes; (void)n_in; (void)out_size;
    const float* x     = (const float*)d_in[0];
    const float* kp_w1 = (const float*)d_in[1];
    const float* kp_b1 = (const float*)d_in[2];
    const float* kp_w2 = (const float*)d_in[3];
    const float* kp_b2 = (const float*)d_in[4];
    const float* qp_w1 = (const float*)d_in[5];
    const float* qp_b1 = (const float*)d_in[6];
    const float* qp_w2 = (const float*)d_in[7];
    const float* qp_b2 = (const float*)d_in[8];
    const float* kh_w1 = (const float*)d_in[9];
    const float* kh_b1 = (const float*)d_in[10];
    const float* kh_w2 = (const float*)d_in[11];
    const float* kh_b2 = (const float*)d_in[12];
    const float* qh_w1 = (const float*)d_in[13];
    const float* qh_b1 = (const float*)d_in[14];
    const float* qh_w2 = (const float*)d_in[15];
    const float* qh_b2 = (const float*)d_in[16];
    const float* v_w   = (const float*)d_in[17];
    const float* v_b   = (const float*)d_in[18];
    const float* ln_g  = (const float*)d_in[19];
    const float* ln_b  = (const float*)d_in[20];
    const float* out_w = (const float*)d_in[21];
    const float* out_b = (const float*)d_in[22];
    float* out = (float*)d_out;

    float *hid, *k2, *q2, *ret, *ret2, *rln;
    cudaGetSymbolAddress((void**)&hid, g_hid);
    cudaGetSymbolAddress((void**)&k2, g_k2);
    cudaGetSymbolAddress((void**)&q2, g_q2);
    cudaGetSymbolAddress((void**)&ret, g_ret);
    cudaGetSymbolAddress((void**)&ret2, g_ret2);
    cudaGetSymbolAddress((void**)&rln, g_rln);

    static bool attr_set = false;
    if (!attr_set) {
        cudaFuncSetAttribute(gemm_fused1, cudaFuncAttributeMaxDynamicSharedMemorySize,
                             GEMM_SMEM_BYTES);
        cudaFuncSetAttribute(layer2_feat, cudaFuncAttributeMaxDynamicSharedMemorySize,
                             GEMM_SMEM_BYTES);
        cudaFuncSetAttribute(attn_kernel, cudaFuncAttributeMaxDynamicSharedMemorySize,
                             ATTN_SMEM_BYTES);
        cudaFuncSetAttribute(gemm_out, cudaFuncAttributeMaxDynamicSharedMemorySize,
                             OUT_SMEM_BYTES);
        attr_set = true;
    }

    dim3 blk(256);

    // 1. fused first layers + V projection
    gemm_fused1<<<dim3(32, 20), blk, GEMM_SMEM_BYTES>>>(
        x, kp_w1, kp_b1, qp_w1, qp_b1, kh_w1, kh_b1, qh_w1, qh_b1, v_w, v_b, hid);

    // 2. fused second layers -> phasor features
    layer2_feat<<<dim3(32, 4), blk, GEMM_SMEM_BYTES>>>(
        hid, kp_w2, kp_b2, qp_w2, qp_b2, kh_w2, kh_b2, qh_w2, qh_b2, k2, q2);

    // 3. balanced causal linear attention (scale fused)
    attn_kernel<<<dim3(24, 2, 4), blk, ATTN_SMEM_BYTES>>>(q2, k2, hid + 1024, ret, ret2);

    // 4. fast LayerNorm
    ln_kernel<<<512, blk>>>(ret, ret2, ln_g, ln_b, rln);

    // 5. output projection + residual
    gemm_out<<<dim3(64, 4), blk, OUT_SMEM_BYTES>>>(rln, out_w, out_b, x, out);
}